// round 6
// baseline (speedup 1.0000x reference)
#include <cuda_runtime.h>
#include <cstdint>
#include <cstddef>

#define NN 16384
#define NE 8192
#define DF 64

// scratch (device-global; no allocations allowed)
__device__ float g_dv[NN];
__device__ float g_de[NE];
__device__ float g_X1[NN * DF];
__device__ float g_Y[NE * DF];

// ---------------- helpers ----------------
__device__ __forceinline__ uint32_t smem_u32(const void* p) {
    return (uint32_t)__cvta_generic_to_shared(p);
}
__device__ __forceinline__ void cp16(uint32_t s, const void* g) {
    asm volatile("cp.async.cg.shared.global [%0], [%1], 16;" :: "r"(s), "l"(g));
}
__device__ __forceinline__ void cp_commit() {
    asm volatile("cp.async.commit_group;" ::: "memory");
}
__device__ __forceinline__ void mma_tf32(float* c, const uint32_t* a, const uint32_t* b) {
    asm volatile(
        "mma.sync.aligned.m16n8k8.row.col.f32.tf32.tf32.f32 "
        "{%0,%1,%2,%3}, {%4,%5,%6,%7}, {%8,%9}, {%0,%1,%2,%3};\n"
        : "+f"(c[0]), "+f"(c[1]), "+f"(c[2]), "+f"(c[3])
        : "r"(a[0]), "r"(a[1]), "r"(a[2]), "r"(a[3]), "r"(b[0]), "r"(b[1]));
}
__device__ __forceinline__ uint32_t tf32_rn(float x) {
    uint32_t r;
    asm("cvt.rna.tf32.f32 %0, %1;" : "=r"(r) : "f"(x));
    return r;
}
__device__ __forceinline__ void tf32_split(float x, uint32_t& hi, uint32_t& lo) {
    hi = tf32_rn(x);
    lo = tf32_rn(x - __uint_as_float(hi));
}

// ---------------- kernel 1: d_v, X1 = d_v*X, d_e partials, zero Y ----------------
// 512 threads: more in-flight loads per SM (was latency-bound at 256).
__global__ __launch_bounds__(512) void k_deg(const float* __restrict__ H,
                                             const float* __restrict__ X) {
    const int t = threadIdx.x;
    const int r0 = blockIdx.x * 128;
    const int wid = t >> 5, lane = t & 31;
    __shared__ float s_wpart[128][16];
    __shared__ float s_dv[128];

    float4 acc_de[4];
#pragma unroll
    for (int i = 0; i < 4; ++i) acc_de[i] = make_float4(0.f, 0.f, 0.f, 0.f);

    for (int r = 0; r < 128; ++r) {
        const float4* row = reinterpret_cast<const float4*>(H + (size_t)(r0 + r) * NE);
        float rs = 0.f;
#pragma unroll
        for (int i = 0; i < 4; ++i) {
            float4 v = row[t + 512 * i];
            acc_de[i].x += v.x; acc_de[i].y += v.y;
            acc_de[i].z += v.z; acc_de[i].w += v.w;
            rs += (v.x + v.y) + (v.z + v.w);
        }
#pragma unroll
        for (int o = 16; o; o >>= 1) rs += __shfl_down_sync(0xffffffffu, rs, o);
        if (lane == 0) s_wpart[r][wid] = rs;
    }
    __syncthreads();
    if (t < 128) {
        float s = 0.f;
#pragma unroll
        for (int w = 0; w < 16; ++w) s += s_wpart[t][w];
        g_dv[r0 + t] = s;
        s_dv[t] = s;
    }
    __syncthreads();
    // X1 = d_v * X for this row block
    for (int idx = t; idx < 128 * DF; idx += 512) {
        int r = idx >> 6, f = idx & 63;
        g_X1[(size_t)(r0 + r) * DF + f] = s_dv[r] * X[(size_t)(r0 + r) * DF + f];
    }
    // zero this block's slice of Y (consumed by gemm1 atomics later in stream order)
    {
        const int base = blockIdx.x * ((NE * DF) / 128);  // 4096 per block
        for (int idx = t; idx < (NE * DF) / 128; idx += 512) g_Y[base + idx] = 0.f;
    }
    // d_e partial sums (each thread owns fixed columns within this block)
#pragma unroll
    for (int i = 0; i < 4; ++i) {
        int e = 4 * (t + 512 * i);
        atomicAdd(&g_de[e + 0], acc_de[i].x);
        atomicAdd(&g_de[e + 1], acc_de[i].y);
        atomicAdd(&g_de[e + 2], acc_de[i].z);
        atomicAdd(&g_de[e + 3], acc_de[i].w);
    }
}

// ---------------- kernel 2: Y += H^T @ X1  (tile 128e x 64f, K split 2, 512 thr) ----------------
__global__ __launch_bounds__(512) void k_gemm1(const float* __restrict__ H) {
    constexpr int PA = 136;  // 136 % 32 == 8 -> conflict-free frag loads
    constexpr int PB = 72;   //  72 % 32 == 8
    constexpr int KC = 16;
    constexpr int NCH = 512; // 8192 / 16 per K half

    __shared__ float As[2][KC * PA];  // [k][e]
    __shared__ float Bs[2][KC * PB];  // [k][f]

    const int t = threadIdx.x;
    const int e0 = blockIdx.x * 128;
    const size_t kbase0 = (size_t)blockIdx.y * 8192;
    const int warp = t >> 5, lane = t & 31, g = lane >> 2, t4 = lane & 3;
    // 16 warps: 4 (M) x 4 (N); warp tile 32 x 16
    const int wm = (warp >> 2) * 32, wn = (warp & 3) * 16;

    float acc[2][2][4];
#pragma unroll
    for (int a = 0; a < 2; ++a)
#pragma unroll
        for (int b = 0; b < 2; ++b)
#pragma unroll
            for (int c = 0; c < 4; ++c) acc[a][b][c] = 0.f;

    auto load_chunk = [&](int ch, int st) {
        const size_t kb = kbase0 + (size_t)ch * KC;
        int row = t >> 5, c4 = t & 31;
        cp16(smem_u32(&As[st][row * PA + c4 * 4]), H + (kb + row) * NE + e0 + c4 * 4);
        if (t < 256) {
            int br = t >> 4, bc = t & 15;
            cp16(smem_u32(&Bs[st][br * PB + bc * 4]), g_X1 + (kb + br) * DF + bc * 4);
        }
    };

    auto compute = [&](int st) {
        const float* A = As[st];
        const float* B = Bs[st];
#pragma unroll
        for (int s = 0; s < 2; ++s) {
            const int k = s * 8 + t4;
            uint32_t ah[2][4], al[2][4], bh[2][2], bl[2][2];
#pragma unroll
            for (int mt = 0; mt < 2; ++mt) {
                int m = wm + mt * 16 + g;
                tf32_split(A[k * PA + m],           ah[mt][0], al[mt][0]);
                tf32_split(A[k * PA + m + 8],       ah[mt][1], al[mt][1]);
                tf32_split(A[(k + 4) * PA + m],     ah[mt][2], al[mt][2]);
                tf32_split(A[(k + 4) * PA + m + 8], ah[mt][3], al[mt][3]);
            }
#pragma unroll
            for (int nt = 0; nt < 2; ++nt) {
                int n = wn + nt * 8 + g;
                tf32_split(B[k * PB + n],       bh[nt][0], bl[nt][0]);
                tf32_split(B[(k + 4) * PB + n], bh[nt][1], bl[nt][1]);
            }
            // 3xTF32: hi*hi + hi*lo + lo*hi
#pragma unroll
            for (int mt = 0; mt < 2; ++mt)
#pragma unroll
                for (int nt = 0; nt < 2; ++nt) mma_tf32(acc[mt][nt], ah[mt], bh[nt]);
#pragma unroll
            for (int mt = 0; mt < 2; ++mt)
#pragma unroll
                for (int nt = 0; nt < 2; ++nt) mma_tf32(acc[mt][nt], ah[mt], bl[nt]);
#pragma unroll
            for (int mt = 0; mt < 2; ++mt)
#pragma unroll
                for (int nt = 0; nt < 2; ++nt) mma_tf32(acc[mt][nt], al[mt], bh[nt]);
        }
    };

    load_chunk(0, 0); cp_commit();
    load_chunk(1, 1); cp_commit();
#pragma unroll 1
    for (int ch = 0; ch < NCH; ++ch) {
        if (ch < NCH - 1) asm volatile("cp.async.wait_group 1;" ::: "memory");
        else              asm volatile("cp.async.wait_group 0;" ::: "memory");
        __syncthreads();
        compute(ch & 1);
        __syncthreads();
        if (ch + 2 < NCH) { load_chunk(ch + 2, ch & 1); cp_commit(); }
    }

    // atomic epilogue (K-split partials)
#pragma unroll
    for (int mt = 0; mt < 2; ++mt) {
        const int e = e0 + wm + mt * 16 + g;
#pragma unroll
        for (int nt = 0; nt < 2; ++nt) {
            const int n = wn + nt * 8 + 2 * t4;
            atomicAdd(&g_Y[(size_t)e * DF + n],           acc[mt][nt][0]);
            atomicAdd(&g_Y[(size_t)e * DF + n + 1],       acc[mt][nt][1]);
            atomicAdd(&g_Y[(size_t)(e + 8) * DF + n],     acc[mt][nt][2]);
            atomicAdd(&g_Y[(size_t)(e + 8) * DF + n + 1], acc[mt][nt][3]);
        }
    }
}

// ---------------- kernel 3: Y *= d_e ----------------
__global__ __launch_bounds__(256) void k_scale_y() {
    const int idx = blockIdx.x * 256 + threadIdx.x;  // over NE*DF/4 f4's
    float4* Y4 = reinterpret_cast<float4*>(g_Y);
    float4 v = Y4[idx];
    const float d = g_de[idx >> 4];
    v.x *= d; v.y *= d; v.z *= d; v.w *= d;
    Y4[idx] = v;
}

// ---------------- kernel 4: out = d_v * (H @ Y)  (512 thr) ----------------
__global__ __launch_bounds__(512) void k_gemm2(const float* __restrict__ H,
                                               float* __restrict__ out) {
    constexpr int PA = 20;   // (20*g + t4) mod 32 all distinct -> conflict-free
    constexpr int PB = 72;
    constexpr int KC = 16;
    constexpr int NCH = 512; // 8192 / 16

    __shared__ float As[2][128 * PA];  // [v][k]
    __shared__ float Bs[2][KC * PB];   // [k][f]

    const int t = threadIdx.x;
    const int v0 = blockIdx.x * 128;
    const int warp = t >> 5, lane = t & 31, g = lane >> 2, t4 = lane & 3;
    const int wm = (warp >> 2) * 32, wn = (warp & 3) * 16;

    float acc[2][2][4];
#pragma unroll
    for (int a = 0; a < 2; ++a)
#pragma unroll
        for (int b = 0; b < 2; ++b)
#pragma unroll
            for (int c = 0; c < 4; ++c) acc[a][b][c] = 0.f;

    auto load_chunk = [&](int ch, int st) {
        const size_t kb = (size_t)ch * KC;
        int row = t >> 2, c4 = t & 3;
        cp16(smem_u32(&As[st][row * PA + c4 * 4]), H + (size_t)(v0 + row) * NE + kb + c4 * 4);
        if (t < 256) {
            int br = t >> 4, bc = t & 15;
            cp16(smem_u32(&Bs[st][br * PB + bc * 4]), g_Y + (kb + br) * DF + bc * 4);
        }
    };

    auto compute = [&](int st) {
        const float* A = As[st];
        const float* B = Bs[st];
#pragma unroll
        for (int s = 0; s < 2; ++s) {
            const int k = s * 8 + t4;
            uint32_t ah[2][4], al[2][4], bh[2][2], bl[2][2];
#pragma unroll
            for (int mt = 0; mt < 2; ++mt) {
                int m = wm + mt * 16 + g;
                tf32_split(A[m * PA + k],           ah[mt][0], al[mt][0]);
                tf32_split(A[(m + 8) * PA + k],     ah[mt][1], al[mt][1]);
                tf32_split(A[m * PA + k + 4],       ah[mt][2], al[mt][2]);
                tf32_split(A[(m + 8) * PA + k + 4], ah[mt][3], al[mt][3]);
            }
#pragma unroll
            for (int nt = 0; nt < 2; ++nt) {
                int n = wn + nt * 8 + g;
                tf32_split(B[k * PB + n],       bh[nt][0], bl[nt][0]);
                tf32_split(B[(k + 4) * PB + n], bh[nt][1], bl[nt][1]);
            }
#pragma unroll
            for (int mt = 0; mt < 2; ++mt)
#pragma unroll
                for (int nt = 0; nt < 2; ++nt) mma_tf32(acc[mt][nt], ah[mt], bh[nt]);
#pragma unroll
            for (int mt = 0; mt < 2; ++mt)
#pragma unroll
                for (int nt = 0; nt < 2; ++nt) mma_tf32(acc[mt][nt], ah[mt], bl[nt]);
#pragma unroll
            for (int mt = 0; mt < 2; ++mt)
#pragma unroll
                for (int nt = 0; nt < 2; ++nt) mma_tf32(acc[mt][nt], al[mt], bh[nt]);
        }
    };

    load_chunk(0, 0); cp_commit();
    load_chunk(1, 1); cp_commit();
#pragma unroll 1
    for (int ch = 0; ch < NCH; ++ch) {
        if (ch < NCH - 1) asm volatile("cp.async.wait_group 1;" ::: "memory");
        else              asm volatile("cp.async.wait_group 0;" ::: "memory");
        __syncthreads();
        compute(ch & 1);
        __syncthreads();
        if (ch + 2 < NCH) { load_chunk(ch + 2, ch & 1); cp_commit(); }
    }

    // direct store epilogue with d_v scaling
#pragma unroll
    for (int mt = 0; mt < 2; ++mt) {
        const int v = v0 + wm + mt * 16 + g;
        const float dlo = g_dv[v];
        const float dhi = g_dv[v + 8];
#pragma unroll
        for (int nt = 0; nt < 2; ++nt) {
            const int n = wn + nt * 8 + 2 * t4;
            float2 lo = make_float2(dlo * acc[mt][nt][0], dlo * acc[mt][nt][1]);
            float2 hi = make_float2(dhi * acc[mt][nt][2], dhi * acc[mt][nt][3]);
            *reinterpret_cast<float2*>(&out[(size_t)v * DF + n]) = lo;
            *reinterpret_cast<float2*>(&out[(size_t)(v + 8) * DF + n]) = hi;
        }
    }
}

// ---------------- launch ----------------
extern "C" void kernel_launch(void* const* d_in, const int* in_sizes, int n_in,
                              void* d_out, int out_size) {
    const float* H = (const float*)d_in[0];
    const float* X = (const float*)d_in[1];
    float* out = (float*)d_out;

    void* de_ptr = nullptr;
    cudaGetSymbolAddress(&de_ptr, g_de);
    cudaMemsetAsync(de_ptr, 0, NE * sizeof(float));

    k_deg<<<128, 512>>>(H, X);
    dim3 grid1(NE / 128, 2);
    k_gemm1<<<grid1, 512>>>(H);
    k_scale_y<<<(NE * DF / 4) / 256, 256>>>();
    k_gemm2<<<NN / 128, 512>>>(H, out);
}

// round 7
// speedup vs baseline: 1.2749x; 1.2749x over previous
#include <cuda_runtime.h>
#include <cuda_bf16.h>
#include <cstdint>
#include <cstddef>

#define NN 16384
#define NE 8192
#define DF 64

// scratch (device-global; no allocations allowed)
__device__ float g_dv[NN];
__device__ float g_de[NE];
__device__ float g_Y[NE * DF];
// pre-split bf16 hi/lo planes, TRANSPOSED ([feature][node/edge]) so GEMM B
// fragments get k-adjacent pairs contiguously.
__device__ __nv_bfloat16 g_X1h[DF * NN];
__device__ __nv_bfloat16 g_X1l[DF * NN];
__device__ __nv_bfloat16 g_Yh[DF * NE];
__device__ __nv_bfloat16 g_Yl[DF * NE];

// ---------------- helpers ----------------
__device__ __forceinline__ uint32_t smem_u32(const void* p) {
    return (uint32_t)__cvta_generic_to_shared(p);
}
__device__ __forceinline__ void cp16(void* s, const void* g) {
    asm volatile("cp.async.cg.shared.global [%0], [%1], 16;" :: "r"(smem_u32(s)), "l"(g));
}
__device__ __forceinline__ void cp_commit() {
    asm volatile("cp.async.commit_group;" ::: "memory");
}
__device__ __forceinline__ void mma_bf16(float* c, const uint32_t* a, const uint32_t* b) {
    asm volatile(
        "mma.sync.aligned.m16n8k16.row.col.f32.bf16.bf16.f32 "
        "{%0,%1,%2,%3}, {%4,%5,%6,%7}, {%8,%9}, {%0,%1,%2,%3};\n"
        : "+f"(c[0]), "+f"(c[1]), "+f"(c[2]), "+f"(c[3])
        : "r"(a[0]), "r"(a[1]), "r"(a[2]), "r"(a[3]), "r"(b[0]), "r"(b[1]));
}
// split two consecutive-k f32 into packed bf16 hi pair + lo pair
// (reg layout: lo half = even k, hi half = odd k, as the MMA expects)
__device__ __forceinline__ void bf16x2_split(float x0, float x1, uint32_t& hi, uint32_t& lo) {
    asm("cvt.rn.bf16x2.f32 %0, %1, %2;" : "=r"(hi) : "f"(x1), "f"(x0));
    float h0 = __uint_as_float(hi << 16);          // bf16->f32 is exact (zero-pad)
    float h1 = __uint_as_float(hi & 0xffff0000u);
    asm("cvt.rn.bf16x2.f32 %0, %1, %2;" : "=r"(lo) : "f"(x1 - h1), "f"(x0 - h0));
}

// ---------------- kernel 1: d_v, d_e partials, X1 planes (transposed), zero Y ----------------
__global__ __launch_bounds__(512) void k_deg(const float* __restrict__ H,
                                             const float* __restrict__ X) {
    const int t = threadIdx.x;
    const int r0 = blockIdx.x * 128;
    const int wid = t >> 5, lane = t & 31;
    __shared__ float s_wpart[128][16];
    __shared__ float s_dv[128];
    __shared__ float s_t[64][133];  // transposed X tile; 133%32=5 -> conflict-free

    float4 acc_de[4];
#pragma unroll
    for (int i = 0; i < 4; ++i) acc_de[i] = make_float4(0.f, 0.f, 0.f, 0.f);

    for (int r = 0; r < 128; ++r) {
        const float4* row = reinterpret_cast<const float4*>(H + (size_t)(r0 + r) * NE);
        float rs = 0.f;
#pragma unroll
        for (int i = 0; i < 4; ++i) {
            float4 v = row[t + 512 * i];
            acc_de[i].x += v.x; acc_de[i].y += v.y;
            acc_de[i].z += v.z; acc_de[i].w += v.w;
            rs += (v.x + v.y) + (v.z + v.w);
        }
#pragma unroll
        for (int o = 16; o; o >>= 1) rs += __shfl_down_sync(0xffffffffu, rs, o);
        if (lane == 0) s_wpart[r][wid] = rs;
    }
    __syncthreads();
    if (t < 128) {
        float s = 0.f;
#pragma unroll
        for (int w = 0; w < 16; ++w) s += s_wpart[t][w];
        g_dv[r0 + t] = s;
        s_dv[t] = s;
    }
    __syncthreads();
    // stage X tile transposed in smem (coalesced global read)
    for (int idx = t; idx < 128 * DF; idx += 512) {
        int r = idx >> 6, f = idx & 63;
        s_t[f][r] = X[(size_t)(r0 + r) * DF + f];
    }
    __syncthreads();
    // write X1 = d_v*X as bf16 hi/lo planes [f][node] (coalesced writes)
    for (int idx = t; idx < DF * 128; idx += 512) {
        int f = idx >> 7, r = idx & 127;
        float x = s_t[f][r] * s_dv[r];
        __nv_bfloat16 h = __float2bfloat16(x);
        __nv_bfloat16 l = __float2bfloat16(x - __bfloat162float(h));
        g_X1h[(size_t)f * NN + r0 + r] = h;
        g_X1l[(size_t)f * NN + r0 + r] = l;
    }
    // zero this block's slice of Y (consumed by gemm1 atomics later in stream order)
    {
        const int base = blockIdx.x * ((NE * DF) / 128);
        for (int idx = t; idx < (NE * DF) / 128; idx += 512) g_Y[base + idx] = 0.f;
    }
    // d_e partial sums
#pragma unroll
    for (int i = 0; i < 4; ++i) {
        int e = 4 * (t + 512 * i);
        atomicAdd(&g_de[e + 0], acc_de[i].x);
        atomicAdd(&g_de[e + 1], acc_de[i].y);
        atomicAdd(&g_de[e + 2], acc_de[i].z);
        atomicAdd(&g_de[e + 3], acc_de[i].w);
    }
}

// ---------------- kernel 2: Y += H^T @ X1  (tile 128e x 64f, K split 2) ----------------
__global__ __launch_bounds__(512) void k_gemm1(const float* __restrict__ H) {
    constexpr int KC = 16;
    constexpr int NCH = 512;  // 8192 nodes per K half / 16
    constexpr int PP = 12;    // plane pitch in u32 words (8 data + 4 pad)

    __shared__ float    Astage[2][KC * 128];          // [k][e] f32
    __shared__ uint32_t Ah[128 * PP], Al[128 * PP];   // [e][kpair] packed bf16
    __shared__ uint32_t Bh[2][DF * PP], Bl[2][DF * PP];

    const int t = threadIdx.x;
    const int e0 = blockIdx.x * 128;
    const int kbase0 = blockIdx.y * 8192;
    const int warp = t >> 5, lane = t & 31, g = lane >> 2, t4 = lane & 3;
    const int wm = (warp >> 2) * 32, wn = (warp & 3) * 16;

    float acc[2][2][4];
#pragma unroll
    for (int a = 0; a < 2; ++a)
#pragma unroll
        for (int b = 0; b < 2; ++b)
#pragma unroll
            for (int c = 0; c < 4; ++c) acc[a][b][c] = 0.f;

    auto load_chunk = [&](int ch, int st) {
        const int kb = kbase0 + ch * KC;
        int row = t >> 5, c = t & 31;
        cp16(&Astage[st][row * 128 + c * 4], H + (size_t)(kb + row) * NE + e0 + c * 4);
        if (t < 256) {
            int f = t >> 2, pl = (t >> 1) & 1, hf = t & 1;
            const __nv_bfloat16* src = (pl ? g_X1l : g_X1h) + (size_t)f * NN + kb + hf * 8;
            uint32_t* dst = (pl ? Bl[st] : Bh[st]) + f * PP + hf * 4;
            cp16(dst, src);
        }
    };

    auto split_a = [&](int st) {
#pragma unroll
        for (int i = 0; i < 2; ++i) {
            int p = t + 512 * i;
            int e = p & 127, kp = p >> 7;
            float x0 = Astage[st][(2 * kp) * 128 + e];
            float x1 = Astage[st][(2 * kp + 1) * 128 + e];
            uint32_t h, l;
            bf16x2_split(x0, x1, h, l);
            Ah[e * PP + kp] = h;
            Al[e * PP + kp] = l;
        }
    };

    auto compute = [&](int st) {
        uint32_t ah[2][4], al[2][4], bh[2][2], bl[2][2];
#pragma unroll
        for (int mt = 0; mt < 2; ++mt) {
            int m0 = wm + mt * 16 + g;
            ah[mt][0] = Ah[m0 * PP + t4];       ah[mt][1] = Ah[(m0 + 8) * PP + t4];
            ah[mt][2] = Ah[m0 * PP + t4 + 4];   ah[mt][3] = Ah[(m0 + 8) * PP + t4 + 4];
            al[mt][0] = Al[m0 * PP + t4];       al[mt][1] = Al[(m0 + 8) * PP + t4];
            al[mt][2] = Al[m0 * PP + t4 + 4];   al[mt][3] = Al[(m0 + 8) * PP + t4 + 4];
        }
#pragma unroll
        for (int nt = 0; nt < 2; ++nt) {
            int n = wn + nt * 8 + g;
            bh[nt][0] = Bh[st][n * PP + t4];  bh[nt][1] = Bh[st][n * PP + t4 + 4];
            bl[nt][0] = Bl[st][n * PP + t4];  bl[nt][1] = Bl[st][n * PP + t4 + 4];
        }
        // 3xBF16: hi*hi + hi*lo + lo*hi
#pragma unroll
        for (int mt = 0; mt < 2; ++mt)
#pragma unroll
            for (int nt = 0; nt < 2; ++nt) mma_bf16(acc[mt][nt], ah[mt], bh[nt]);
#pragma unroll
        for (int mt = 0; mt < 2; ++mt)
#pragma unroll
            for (int nt = 0; nt < 2; ++nt) mma_bf16(acc[mt][nt], ah[mt], bl[nt]);
#pragma unroll
        for (int mt = 0; mt < 2; ++mt)
#pragma unroll
            for (int nt = 0; nt < 2; ++nt) mma_bf16(acc[mt][nt], al[mt], bh[nt]);
    };

    load_chunk(0, 0); cp_commit();
    load_chunk(1, 1); cp_commit();
#pragma unroll 1
    for (int ch = 0; ch < NCH; ++ch) {
        if (ch < NCH - 1) asm volatile("cp.async.wait_group 1;" ::: "memory");
        else              asm volatile("cp.async.wait_group 0;" ::: "memory");
        __syncthreads();
        split_a(ch & 1);
        __syncthreads();
        compute(ch & 1);
        __syncthreads();
        if (ch + 2 < NCH) { load_chunk(ch + 2, ch & 1); cp_commit(); }
    }

    // atomic epilogue (K-split partials)
#pragma unroll
    for (int mt = 0; mt < 2; ++mt) {
        const int e = e0 + wm + mt * 16 + g;
#pragma unroll
        for (int nt = 0; nt < 2; ++nt) {
            const int n = wn + nt * 8 + 2 * t4;
            atomicAdd(&g_Y[(size_t)e * DF + n],           acc[mt][nt][0]);
            atomicAdd(&g_Y[(size_t)e * DF + n + 1],       acc[mt][nt][1]);
            atomicAdd(&g_Y[(size_t)(e + 8) * DF + n],     acc[mt][nt][2]);
            atomicAdd(&g_Y[(size_t)(e + 8) * DF + n + 1], acc[mt][nt][3]);
        }
    }
}

// ---------------- kernel 3: Y *= d_e, emit transposed bf16 hi/lo planes ----------------
__global__ __launch_bounds__(256) void k_scale_y() {
    const int idx = blockIdx.x * 256 + threadIdx.x;  // over NE*DF
    const int e = idx & (NE - 1);
    const int f = idx >> 13;
    float v = g_Y[(size_t)e * DF + f] * g_de[e];  // strided read (L2-resident)
    __nv_bfloat16 h = __float2bfloat16(v);
    __nv_bfloat16 l = __float2bfloat16(v - __bfloat162float(h));
    g_Yh[(size_t)f * NE + e] = h;  // coalesced write
    g_Yl[(size_t)f * NE + e] = l;
}

// ---------------- kernel 4: out = d_v * (H @ Y) ----------------
__global__ __launch_bounds__(512) void k_gemm2(const float* __restrict__ H,
                                               float* __restrict__ out) {
    constexpr int KC = 16;
    constexpr int NCH = 512;  // 8192 edges / 16
    constexpr int PP = 12;
    constexpr int PAW = 20;   // f32 stage pitch (16 data + 4 pad), rows 16B-aligned

    __shared__ float    Astage[2][128 * PAW];         // [v][k] f32
    __shared__ uint32_t Ah[128 * PP], Al[128 * PP];   // [v][kpair]
    __shared__ uint32_t Bh[2][DF * PP], Bl[2][DF * PP];

    const int t = threadIdx.x;
    const int v0 = blockIdx.x * 128;
    const int warp = t >> 5, lane = t & 31, g = lane >> 2, t4 = lane & 3;
    const int wm = (warp >> 2) * 32, wn = (warp & 3) * 16;

    float acc[2][2][4];
#pragma unroll
    for (int a = 0; a < 2; ++a)
#pragma unroll
        for (int b = 0; b < 2; ++b)
#pragma unroll
            for (int c = 0; c < 4; ++c) acc[a][b][c] = 0.f;

    auto load_chunk = [&](int ch, int st) {
        const int kb = ch * KC;
        int v = t >> 2, q = t & 3;
        cp16(&Astage[st][v * PAW + q * 4], H + (size_t)(v0 + v) * NE + kb + q * 4);
        if (t < 256) {
            int f = t >> 2, pl = (t >> 1) & 1, hf = t & 1;
            const __nv_bfloat16* src = (pl ? g_Yl : g_Yh) + (size_t)f * NE + kb + hf * 8;
            uint32_t* dst = (pl ? Bl[st] : Bh[st]) + f * PP + hf * 4;
            cp16(dst, src);
        }
    };

    auto split_a = [&](int st) {
#pragma unroll
        for (int i = 0; i < 2; ++i) {
            int p = t + 512 * i;
            int v = p >> 3, kp = p & 7;
            float x0 = Astage[st][v * PAW + 2 * kp];
            float x1 = Astage[st][v * PAW + 2 * kp + 1];
            uint32_t h, l;
            bf16x2_split(x0, x1, h, l);
            Ah[v * PP + kp] = h;
            Al[v * PP + kp] = l;
        }
    };

    auto compute = [&](int st) {
        uint32_t ah[2][4], al[2][4], bh[2][2], bl[2][2];
#pragma unroll
        for (int mt = 0; mt < 2; ++mt) {
            int m0 = wm + mt * 16 + g;
            ah[mt][0] = Ah[m0 * PP + t4];       ah[mt][1] = Ah[(m0 + 8) * PP + t4];
            ah[mt][2] = Ah[m0 * PP + t4 + 4];   ah[mt][3] = Ah[(m0 + 8) * PP + t4 + 4];
            al[mt][0] = Al[m0 * PP + t4];       al[mt][1] = Al[(m0 + 8) * PP + t4];
            al[mt][2] = Al[m0 * PP + t4 + 4];   al[mt][3] = Al[(m0 + 8) * PP + t4 + 4];
        }
#pragma unroll
        for (int nt = 0; nt < 2; ++nt) {
            int n = wn + nt * 8 + g;
            bh[nt][0] = Bh[st][n * PP + t4];  bh[nt][1] = Bh[st][n * PP + t4 + 4];
            bl[nt][0] = Bl[st][n * PP + t4];  bl[nt][1] = Bl[st][n * PP + t4 + 4];
        }
#pragma unroll
        for (int mt = 0; mt < 2; ++mt)
#pragma unroll
            for (int nt = 0; nt < 2; ++nt) mma_bf16(acc[mt][nt], ah[mt], bh[nt]);
#pragma unroll
        for (int mt = 0; mt < 2; ++mt)
#pragma unroll
            for (int nt = 0; nt < 2; ++nt) mma_bf16(acc[mt][nt], ah[mt], bl[nt]);
#pragma unroll
        for (int mt = 0; mt < 2; ++mt)
#pragma unroll
            for (int nt = 0; nt < 2; ++nt) mma_bf16(acc[mt][nt], al[mt], bh[nt]);
    };

    load_chunk(0, 0); cp_commit();
    load_chunk(1, 1); cp_commit();
#pragma unroll 1
    for (int ch = 0; ch < NCH; ++ch) {
        if (ch < NCH - 1) asm volatile("cp.async.wait_group 1;" ::: "memory");
        else              asm volatile("cp.async.wait_group 0;" ::: "memory");
        __syncthreads();
        split_a(ch & 1);
        __syncthreads();
        compute(ch & 1);
        __syncthreads();
        if (ch + 2 < NCH) { load_chunk(ch + 2, ch & 1); cp_commit(); }
    }

    // direct store epilogue with d_v scaling
#pragma unroll
    for (int mt = 0; mt < 2; ++mt) {
        const int v = v0 + wm + mt * 16 + g;
        const float dlo = g_dv[v];
        const float dhi = g_dv[v + 8];
#pragma unroll
        for (int nt = 0; nt < 2; ++nt) {
            const int n = wn + nt * 8 + 2 * t4;
            float2 lo = make_float2(dlo * acc[mt][nt][0], dlo * acc[mt][nt][1]);
            float2 hi = make_float2(dhi * acc[mt][nt][2], dhi * acc[mt][nt][3]);
            *reinterpret_cast<float2*>(&out[(size_t)v * DF + n]) = lo;
            *reinterpret_cast<float2*>(&out[(size_t)(v + 8) * DF + n]) = hi;
        }
    }
}

// ---------------- launch ----------------
extern "C" void kernel_launch(void* const* d_in, const int* in_sizes, int n_in,
                              void* d_out, int out_size) {
    const float* H = (const float*)d_in[0];
    const float* X = (const float*)d_in[1];
    float* out = (float*)d_out;

    void* de_ptr = nullptr;
    cudaGetSymbolAddress(&de_ptr, g_de);
    cudaMemsetAsync(de_ptr, 0, NE * sizeof(float));

    k_deg<<<128, 512>>>(H, X);
    dim3 grid1(NE / 128, 2);
    k_gemm1<<<grid1, 512>>>(H);
    k_scale_y<<<(NE * DF) / 256, 256>>>();
    k_gemm2<<<NN / 128, 512>>>(H, out);
}

// round 8
// speedup vs baseline: 1.6151x; 1.2668x over previous
#include <cuda_runtime.h>
#include <cuda_bf16.h>
#include <cstdint>
#include <cstddef>

#define NN 16384
#define NE 8192
#define DF 64

// scratch (device-global; no allocations allowed)
__device__ float g_dv[NN];
__device__ float g_de[NE];
__device__ float g_Y[NE * DF];
// pre-split bf16 hi/lo planes of H, native [node][edge] layout.
// Serves gemm2 A directly (ldmatrix) and gemm1 A via ldmatrix.trans.
__device__ __nv_bfloat16 g_Hh[(size_t)NN * NE];
__device__ __nv_bfloat16 g_Hl[(size_t)NN * NE];
// B-operand planes, TRANSPOSED ([feature][node/edge]) for k-contiguous fragments.
__device__ __nv_bfloat16 g_X1h[DF * NN];
__device__ __nv_bfloat16 g_X1l[DF * NN];
__device__ __nv_bfloat16 g_Yh[DF * NE];
__device__ __nv_bfloat16 g_Yl[DF * NE];

// ---------------- helpers ----------------
__device__ __forceinline__ uint32_t smem_u32(const void* p) {
    return (uint32_t)__cvta_generic_to_shared(p);
}
__device__ __forceinline__ void cp16(void* s, const void* g) {
    asm volatile("cp.async.cg.shared.global [%0], [%1], 16;" :: "r"(smem_u32(s)), "l"(g));
}
__device__ __forceinline__ void cp_commit() {
    asm volatile("cp.async.commit_group;" ::: "memory");
}
__device__ __forceinline__ void mma_bf16(float* c, const uint32_t* a, const uint32_t* b) {
    asm volatile(
        "mma.sync.aligned.m16n8k16.row.col.f32.bf16.bf16.f32 "
        "{%0,%1,%2,%3}, {%4,%5,%6,%7}, {%8,%9}, {%0,%1,%2,%3};\n"
        : "+f"(c[0]), "+f"(c[1]), "+f"(c[2]), "+f"(c[3])
        : "r"(a[0]), "r"(a[1]), "r"(a[2]), "r"(a[3]), "r"(b[0]), "r"(b[1]));
}
__device__ __forceinline__ void ldsm4(uint32_t* r, uint32_t a) {
    asm volatile("ldmatrix.sync.aligned.m8n8.x4.shared.b16 {%0,%1,%2,%3}, [%4];"
                 : "=r"(r[0]), "=r"(r[1]), "=r"(r[2]), "=r"(r[3]) : "r"(a));
}
__device__ __forceinline__ void ldsm4t(uint32_t* r, uint32_t a) {
    asm volatile("ldmatrix.sync.aligned.m8n8.x4.trans.shared.b16 {%0,%1,%2,%3}, [%4];"
                 : "=r"(r[0]), "=r"(r[1]), "=r"(r[2]), "=r"(r[3]) : "r"(a));
}
// split two consecutive f32 into packed bf16 hi pair + lo pair (x0 in low half)
__device__ __forceinline__ void bf16x2_split(float x0, float x1, uint32_t& hi, uint32_t& lo) {
    asm("cvt.rn.bf16x2.f32 %0, %1, %2;" : "=r"(hi) : "f"(x1), "f"(x0));
    float h0 = __uint_as_float(hi << 16);          // bf16->f32 exact
    float h1 = __uint_as_float(hi & 0xffff0000u);
    asm("cvt.rn.bf16x2.f32 %0, %1, %2;" : "=r"(lo) : "f"(x1 - h1), "f"(x0 - h0));
}

// ---------------- kernel 1: d_v, d_e partials, H planes, X1 planes, zero Y ----------------
__global__ __launch_bounds__(512) void k_deg(const float* __restrict__ H,
                                             const float* __restrict__ X) {
    const int t = threadIdx.x;
    const int r0 = blockIdx.x * 128;
    const int wid = t >> 5, lane = t & 31;
    __shared__ float s_wpart[128][16];
    __shared__ float s_dv[128];
    __shared__ float s_t[64][133];  // transposed X tile; 133%32=5 -> conflict-free

    float4 acc_de[4];
#pragma unroll
    for (int i = 0; i < 4; ++i) acc_de[i] = make_float4(0.f, 0.f, 0.f, 0.f);

    for (int r = 0; r < 128; ++r) {
        const float4* row = reinterpret_cast<const float4*>(H + (size_t)(r0 + r) * NE);
        uint2* dh = reinterpret_cast<uint2*>(g_Hh + (size_t)(r0 + r) * NE);
        uint2* dl = reinterpret_cast<uint2*>(g_Hl + (size_t)(r0 + r) * NE);
        float rs = 0.f;
#pragma unroll
        for (int i = 0; i < 4; ++i) {
            float4 v = row[t + 512 * i];
            acc_de[i].x += v.x; acc_de[i].y += v.y;
            acc_de[i].z += v.z; acc_de[i].w += v.w;
            rs += (v.x + v.y) + (v.z + v.w);
            uint32_t h0, l0, h1, l1;
            bf16x2_split(v.x, v.y, h0, l0);
            bf16x2_split(v.z, v.w, h1, l1);
            dh[t + 512 * i] = make_uint2(h0, h1);
            dl[t + 512 * i] = make_uint2(l0, l1);
        }
#pragma unroll
        for (int o = 16; o; o >>= 1) rs += __shfl_down_sync(0xffffffffu, rs, o);
        if (lane == 0) s_wpart[r][wid] = rs;
    }
    __syncthreads();
    if (t < 128) {
        float s = 0.f;
#pragma unroll
        for (int w = 0; w < 16; ++w) s += s_wpart[t][w];
        g_dv[r0 + t] = s;
        s_dv[t] = s;
    }
    __syncthreads();
    // stage X tile transposed in smem (coalesced global read)
    for (int idx = t; idx < 128 * DF; idx += 512) {
        int r = idx >> 6, f = idx & 63;
        s_t[f][r] = X[(size_t)(r0 + r) * DF + f];
    }
    __syncthreads();
    // write X1 = d_v*X as bf16 hi/lo planes [f][node] (coalesced writes)
    for (int idx = t; idx < DF * 128; idx += 512) {
        int f = idx >> 7, r = idx & 127;
        float x = s_t[f][r] * s_dv[r];
        __nv_bfloat16 h = __float2bfloat16(x);
        __nv_bfloat16 l = __float2bfloat16(x - __bfloat162float(h));
        g_X1h[(size_t)f * NN + r0 + r] = h;
        g_X1l[(size_t)f * NN + r0 + r] = l;
    }
    // zero this block's slice of Y
    {
        const int base = blockIdx.x * ((NE * DF) / 128);
        for (int idx = t; idx < (NE * DF) / 128; idx += 512) g_Y[base + idx] = 0.f;
    }
    // d_e partial sums
#pragma unroll
    for (int i = 0; i < 4; ++i) {
        int e = 4 * (t + 512 * i);
        atomicAdd(&g_de[e + 0], acc_de[i].x);
        atomicAdd(&g_de[e + 1], acc_de[i].y);
        atomicAdd(&g_de[e + 2], acc_de[i].z);
        atomicAdd(&g_de[e + 3], acc_de[i].w);
    }
}

// ---------------- kernel 2: Y += H^T @ X1  (tile 128e x 64f, K split 2, KC=32) ----------------
// A tiles [k][e] from H planes via ldmatrix.trans; B from X1 planes.
__global__ __launch_bounds__(512) void k_gemm1() {
    constexpr int KC = 32;
    constexpr int NCH = 256;   // 8192 per K half / 32
    constexpr int AP = 136;    // bf16 pitch: 272B rows -> LDSM rows hit distinct bank quads
    constexpr int BPW = 20;    // u32 words per f-row (16 data + 4 pad)
    constexpr int ASTG = KC * AP;       // bf16 per stage per plane
    constexpr int BSTG = DF * BPW;      // words per stage per plane

    extern __shared__ char smem[];
    __nv_bfloat16* Ah = (__nv_bfloat16*)smem;          // [2][ASTG]
    __nv_bfloat16* Al = Ah + 2 * ASTG;                 // [2][ASTG]
    uint32_t* Bh = (uint32_t*)(Al + 2 * ASTG);         // [2][BSTG]
    uint32_t* Bl = Bh + 2 * BSTG;                      // [2][BSTG]

    const int t = threadIdx.x;
    const int e0 = blockIdx.x * 128;
    const int kbase0 = blockIdx.y * 8192;
    const int warp = t >> 5, lane = t & 31, g = lane >> 2, t4 = lane & 3;
    const int wm = (warp >> 2) * 32, wn = (warp & 3) * 16;
    // ldmatrix.trans lane address pieces: stored [k][m]
    const int krow = ((lane >> 4) & 1) * 8 + (lane & 7);  // 0..15 within k16 block
    const int mcol8 = ((lane >> 3) & 1) * 8;

    float acc[2][2][4];
#pragma unroll
    for (int a = 0; a < 2; ++a)
#pragma unroll
        for (int b = 0; b < 2; ++b)
#pragma unroll
            for (int c = 0; c < 4; ++c) acc[a][b][c] = 0.f;

    auto load_chunk = [&](int ch, int st) {
        const int kb = kbase0 + ch * KC;
        {   // A planes: 32 rows x 16 x 16B chunks each
            int r = t >> 4, c = t & 15;
            cp16(Ah + st * ASTG + r * AP + c * 8, g_Hh + (size_t)(kb + r) * NE + e0 + c * 8);
            cp16(Al + st * ASTG + r * AP + c * 8, g_Hl + (size_t)(kb + r) * NE + e0 + c * 8);
        }
        {   // B planes: 64 f-rows x 4 chunks x 2 planes
            int pl = t >> 8, f = (t >> 2) & 63, c = t & 3;
            const __nv_bfloat16* src = (pl ? g_X1l : g_X1h) + (size_t)f * NN + kb + c * 8;
            uint32_t* dst = (pl ? Bl : Bh) + st * BSTG + f * BPW + c * 4;
            cp16(dst, src);
        }
    };

    auto compute = [&](int st) {
        const uint32_t abase_h = smem_u32(Ah + st * ASTG);
        const uint32_t abase_l = smem_u32(Al + st * ASTG);
        const uint32_t* BH = Bh + st * BSTG;
        const uint32_t* BL = Bl + st * BSTG;
#pragma unroll
        for (int s = 0; s < 2; ++s) {
            uint32_t ah[2][4], al[2][4], bh[2][2], bl[2][2];
#pragma unroll
            for (int mt = 0; mt < 2; ++mt) {
                uint32_t off = (uint32_t)(((s * 16 + krow) * AP + wm + mt * 16 + mcol8) * 2);
                ldsm4t(ah[mt], abase_h + off);
                ldsm4t(al[mt], abase_l + off);
            }
#pragma unroll
            for (int nt = 0; nt < 2; ++nt) {
                int n = wn + nt * 8 + g;
                bh[nt][0] = BH[n * BPW + s * 8 + t4];  bh[nt][1] = BH[n * BPW + s * 8 + t4 + 4];
                bl[nt][0] = BL[n * BPW + s * 8 + t4];  bl[nt][1] = BL[n * BPW + s * 8 + t4 + 4];
            }
            // 3xBF16: hi*hi + hi*lo + lo*hi
#pragma unroll
            for (int mt = 0; mt < 2; ++mt)
#pragma unroll
                for (int nt = 0; nt < 2; ++nt) mma_bf16(acc[mt][nt], ah[mt], bh[nt]);
#pragma unroll
            for (int mt = 0; mt < 2; ++mt)
#pragma unroll
                for (int nt = 0; nt < 2; ++nt) mma_bf16(acc[mt][nt], ah[mt], bl[nt]);
#pragma unroll
            for (int mt = 0; mt < 2; ++mt)
#pragma unroll
                for (int nt = 0; nt < 2; ++nt) mma_bf16(acc[mt][nt], al[mt], bh[nt]);
        }
    };

    load_chunk(0, 0); cp_commit();
    load_chunk(1, 1); cp_commit();
#pragma unroll 1
    for (int ch = 0; ch < NCH; ++ch) {
        if (ch < NCH - 1) asm volatile("cp.async.wait_group 1;" ::: "memory");
        else              asm volatile("cp.async.wait_group 0;" ::: "memory");
        __syncthreads();
        compute(ch & 1);
        __syncthreads();
        if (ch + 2 < NCH) { load_chunk(ch + 2, ch & 1); cp_commit(); }
    }

    // atomic epilogue (K-split partials)
#pragma unroll
    for (int mt = 0; mt < 2; ++mt) {
        const int e = e0 + wm + mt * 16 + g;
#pragma unroll
        for (int nt = 0; nt < 2; ++nt) {
            const int n = wn + nt * 8 + 2 * t4;
            atomicAdd(&g_Y[(size_t)e * DF + n],           acc[mt][nt][0]);
            atomicAdd(&g_Y[(size_t)e * DF + n + 1],       acc[mt][nt][1]);
            atomicAdd(&g_Y[(size_t)(e + 8) * DF + n],     acc[mt][nt][2]);
            atomicAdd(&g_Y[(size_t)(e + 8) * DF + n + 1], acc[mt][nt][3]);
        }
    }
}

// ---------------- kernel 3: Y *= d_e, emit transposed bf16 hi/lo planes ----------------
__global__ __launch_bounds__(256) void k_scale_y() {
    const int idx = blockIdx.x * 256 + threadIdx.x;  // over NE*DF
    const int e = idx & (NE - 1);
    const int f = idx >> 13;
    float v = g_Y[(size_t)e * DF + f] * g_de[e];  // strided read (L2-resident)
    __nv_bfloat16 h = __float2bfloat16(v);
    __nv_bfloat16 l = __float2bfloat16(v - __bfloat162float(h));
    g_Yh[(size_t)f * NE + e] = h;  // coalesced write
    g_Yl[(size_t)f * NE + e] = l;
}

// ---------------- kernel 4: out = d_v * (H @ Y)  (KC=32, ldmatrix A) ----------------
__global__ __launch_bounds__(512) void k_gemm2(float* __restrict__ out) {
    constexpr int KC = 32;
    constexpr int NCH = 256;   // 8192 / 32
    constexpr int AP = 40;     // bf16 pitch: 80B rows -> LDSM conflict-free
    constexpr int BPW = 20;
    constexpr int ASTG = 128 * AP;
    constexpr int BSTG = DF * BPW;

    extern __shared__ char smem[];
    __nv_bfloat16* Ah = (__nv_bfloat16*)smem;          // [2][ASTG]
    __nv_bfloat16* Al = Ah + 2 * ASTG;
    uint32_t* Bh = (uint32_t*)(Al + 2 * ASTG);         // [2][BSTG]
    uint32_t* Bl = Bh + 2 * BSTG;

    const int t = threadIdx.x;
    const int v0 = blockIdx.x * 128;
    const int warp = t >> 5, lane = t & 31, g = lane >> 2, t4 = lane & 3;
    const int wm = (warp >> 2) * 32, wn = (warp & 3) * 16;
    // ldmatrix (non-trans) lane address pieces: stored [m][k]
    const int mrow = ((lane >> 3) & 1) * 8 + (lane & 7);
    const int kcol8 = ((lane >> 4) & 1) * 8;

    float acc[2][2][4];
#pragma unroll
    for (int a = 0; a < 2; ++a)
#pragma unroll
        for (int b = 0; b < 2; ++b)
#pragma unroll
            for (int c = 0; c < 4; ++c) acc[a][b][c] = 0.f;

    auto load_chunk = [&](int ch, int st) {
        const int kb = ch * KC;
        {   // A planes: 128 rows x 4 x 16B chunks each
            int v = t >> 2, c = t & 3;
            cp16(Ah + st * ASTG + v * AP + c * 8, g_Hh + (size_t)(v0 + v) * NE + kb + c * 8);
            cp16(Al + st * ASTG + v * AP + c * 8, g_Hl + (size_t)(v0 + v) * NE + kb + c * 8);
        }
        {   // B planes
            int pl = t >> 8, f = (t >> 2) & 63, c = t & 3;
            const __nv_bfloat16* src = (pl ? g_Yl : g_Yh) + (size_t)f * NE + kb + c * 8;
            uint32_t* dst = (pl ? Bl : Bh) + st * BSTG + f * BPW + c * 4;
            cp16(dst, src);
        }
    };

    auto compute = [&](int st) {
        const uint32_t abase_h = smem_u32(Ah + st * ASTG);
        const uint32_t abase_l = smem_u32(Al + st * ASTG);
        const uint32_t* BH = Bh + st * BSTG;
        const uint32_t* BL = Bl + st * BSTG;
#pragma unroll
        for (int s = 0; s < 2; ++s) {
            uint32_t ah[2][4], al[2][4], bh[2][2], bl[2][2];
#pragma unroll
            for (int mt = 0; mt < 2; ++mt) {
                uint32_t off = (uint32_t)(((wm + mt * 16 + mrow) * AP + s * 16 + kcol8) * 2);
                ldsm4(ah[mt], abase_h + off);
                ldsm4(al[mt], abase_l + off);
            }
#pragma unroll
            for (int nt = 0; nt < 2; ++nt) {
                int n = wn + nt * 8 + g;
                bh[nt][0] = BH[n * BPW + s * 8 + t4];  bh[nt][1] = BH[n * BPW + s * 8 + t4 + 4];
                bl[nt][0] = BL[n * BPW + s * 8 + t4];  bl[nt][1] = BL[n * BPW + s * 8 + t4 + 4];
            }
#pragma unroll
            for (int mt = 0; mt < 2; ++mt)
#pragma unroll
                for (int nt = 0; nt < 2; ++nt) mma_bf16(acc[mt][nt], ah[mt], bh[nt]);
#pragma unroll
            for (int mt = 0; mt < 2; ++mt)
#pragma unroll
                for (int nt = 0; nt < 2; ++nt) mma_bf16(acc[mt][nt], ah[mt], bl[nt]);
#pragma unroll
            for (int mt = 0; mt < 2; ++mt)
#pragma unroll
                for (int nt = 0; nt < 2; ++nt) mma_bf16(acc[mt][nt], al[mt], bh[nt]);
        }
    };

    load_chunk(0, 0); cp_commit();
    load_chunk(1, 1); cp_commit();
#pragma unroll 1
    for (int ch = 0; ch < NCH; ++ch) {
        if (ch < NCH - 1) asm volatile("cp.async.wait_group 1;" ::: "memory");
        else              asm volatile("cp.async.wait_group 0;" ::: "memory");
        __syncthreads();
        compute(ch & 1);
        __syncthreads();
        if (ch + 2 < NCH) { load_chunk(ch + 2, ch & 1); cp_commit(); }
    }

    // direct store epilogue with d_v scaling
#pragma unroll
    for (int mt = 0; mt < 2; ++mt) {
        const int v = v0 + wm + mt * 16 + g;
        const float dlo = g_dv[v];
        const float dhi = g_dv[v + 8];
#pragma unroll
        for (int nt = 0; nt < 2; ++nt) {
            const int n = wn + nt * 8 + 2 * t4;
            float2 lo = make_float2(dlo * acc[mt][nt][0], dlo * acc[mt][nt][1]);
            float2 hi = make_float2(dhi * acc[mt][nt][2], dhi * acc[mt][nt][3]);
            *reinterpret_cast<float2*>(&out[(size_t)v * DF + n]) = lo;
            *reinterpret_cast<float2*>(&out[(size_t)(v + 8) * DF + n]) = hi;
        }
    }
}

// ---------------- launch ----------------
extern "C" void kernel_launch(void* const* d_in, const int* in_sizes, int n_in,
                              void* d_out, int out_size) {
    const float* H = (const float*)d_in[0];
    const float* X = (const float*)d_in[1];
    float* out = (float*)d_out;

    // dynamic smem: gemm1 = 2*2*32*136*2 + 2*2*64*20*4 = 55296 B
    //               gemm2 = 2*2*128*40*2 + 2*2*64*20*4 = 61440 B
    static bool attr_done = false;
    if (!attr_done) {
        cudaFuncSetAttribute(k_gemm1, cudaFuncAttributeMaxDynamicSharedMemorySize, 55296);
        cudaFuncSetAttribute(k_gemm2, cudaFuncAttributeMaxDynamicSharedMemorySize, 61440);
        attr_done = true;
    }

    void* de_ptr = nullptr;
    cudaGetSymbolAddress(&de_ptr, g_de);
    cudaMemsetAsync(de_ptr, 0, NE * sizeof(float));

    k_deg<<<128, 512>>>(H, X);
    dim3 grid1(NE / 128, 2);
    k_gemm1<<<grid1, 512, 55296>>>();
    k_scale_y<<<(NE * DF) / 256, 256>>>();
    k_gemm2<<<NN / 128, 512, 61440>>>(out);
}

// round 9
// speedup vs baseline: 1.6378x; 1.0141x over previous
#include <cuda_runtime.h>
#include <cuda_bf16.h>
#include <cstdint>
#include <cstddef>

#define NN 16384
#define NE 8192
#define DF 64

// scratch (device-global; no allocations allowed)
__device__ float g_dv[NN];
__device__ float g_de[NE];
__device__ float g_Y[NE * DF];
// pre-split bf16 hi/lo planes of H, native [node][edge] layout.
__device__ __nv_bfloat16 g_Hh[(size_t)NN * NE];
__device__ __nv_bfloat16 g_Hl[(size_t)NN * NE];
// B-operand planes, TRANSPOSED ([feature][node/edge]) for k-contiguous fragments.
__device__ __nv_bfloat16 g_X1h[DF * NN];
__device__ __nv_bfloat16 g_X1l[DF * NN];
__device__ __nv_bfloat16 g_Yh[DF * NE];
__device__ __nv_bfloat16 g_Yl[DF * NE];

// ---------------- helpers ----------------
__device__ __forceinline__ uint32_t smem_u32(const void* p) {
    return (uint32_t)__cvta_generic_to_shared(p);
}
__device__ __forceinline__ void cp16(void* s, const void* g) {
    asm volatile("cp.async.cg.shared.global [%0], [%1], 16;" :: "r"(smem_u32(s)), "l"(g));
}
__device__ __forceinline__ void cp_commit() {
    asm volatile("cp.async.commit_group;" ::: "memory");
}
__device__ __forceinline__ void mma_bf16(float* c, const uint32_t* a, const uint32_t* b) {
    asm volatile(
        "mma.sync.aligned.m16n8k16.row.col.f32.bf16.bf16.f32 "
        "{%0,%1,%2,%3}, {%4,%5,%6,%7}, {%8,%9}, {%0,%1,%2,%3};\n"
        : "+f"(c[0]), "+f"(c[1]), "+f"(c[2]), "+f"(c[3])
        : "r"(a[0]), "r"(a[1]), "r"(a[2]), "r"(a[3]), "r"(b[0]), "r"(b[1]));
}
__device__ __forceinline__ void ldsm4(uint32_t* r, uint32_t a) {
    asm volatile("ldmatrix.sync.aligned.m8n8.x4.shared.b16 {%0,%1,%2,%3}, [%4];"
                 : "=r"(r[0]), "=r"(r[1]), "=r"(r[2]), "=r"(r[3]) : "r"(a));
}
__device__ __forceinline__ void ldsm4t(uint32_t* r, uint32_t a) {
    asm volatile("ldmatrix.sync.aligned.m8n8.x4.trans.shared.b16 {%0,%1,%2,%3}, [%4];"
                 : "=r"(r[0]), "=r"(r[1]), "=r"(r[2]), "=r"(r[3]) : "r"(a));
}
// split two consecutive f32 into packed bf16 hi pair + lo pair (x0 in low half)
__device__ __forceinline__ void bf16x2_split(float x0, float x1, uint32_t& hi, uint32_t& lo) {
    asm("cvt.rn.bf16x2.f32 %0, %1, %2;" : "=r"(hi) : "f"(x1), "f"(x0));
    float h0 = __uint_as_float(hi << 16);          // bf16->f32 exact
    float h1 = __uint_as_float(hi & 0xffff0000u);
    asm("cvt.rn.bf16x2.f32 %0, %1, %2;" : "=r"(lo) : "f"(x1 - h1), "f"(x0 - h0));
}

// ---------------- kernel 1: d_v, d_e partials, H planes, X1 planes, zero Y ----------------
__global__ __launch_bounds__(512) void k_deg(const float* __restrict__ H,
                                             const float* __restrict__ X) {
    const int t = threadIdx.x;
    const int r0 = blockIdx.x * 128;
    const int wid = t >> 5, lane = t & 31;
    __shared__ float s_wpart[128][16];
    __shared__ float s_dv[128];
    __shared__ float s_t[64][133];  // transposed X tile; 133%32=5 -> conflict-free

    float4 acc_de[4];
#pragma unroll
    for (int i = 0; i < 4; ++i) acc_de[i] = make_float4(0.f, 0.f, 0.f, 0.f);

    for (int r = 0; r < 128; ++r) {
        const float4* row = reinterpret_cast<const float4*>(H + (size_t)(r0 + r) * NE);
        uint2* dh = reinterpret_cast<uint2*>(g_Hh + (size_t)(r0 + r) * NE);
        uint2* dl = reinterpret_cast<uint2*>(g_Hl + (size_t)(r0 + r) * NE);
        float rs = 0.f;
#pragma unroll
        for (int i = 0; i < 4; ++i) {
            float4 v = row[t + 512 * i];
            acc_de[i].x += v.x; acc_de[i].y += v.y;
            acc_de[i].z += v.z; acc_de[i].w += v.w;
            rs += (v.x + v.y) + (v.z + v.w);
            uint32_t h0, l0, h1, l1;
            bf16x2_split(v.x, v.y, h0, l0);
            bf16x2_split(v.z, v.w, h1, l1);
            dh[t + 512 * i] = make_uint2(h0, h1);
            dl[t + 512 * i] = make_uint2(l0, l1);
        }
#pragma unroll
        for (int o = 16; o; o >>= 1) rs += __shfl_down_sync(0xffffffffu, rs, o);
        if (lane == 0) s_wpart[r][wid] = rs;
    }
    __syncthreads();
    if (t < 128) {
        float s = 0.f;
#pragma unroll
        for (int w = 0; w < 16; ++w) s += s_wpart[t][w];
        g_dv[r0 + t] = s;
        s_dv[t] = s;
    }
    __syncthreads();
    for (int idx = t; idx < 128 * DF; idx += 512) {
        int r = idx >> 6, f = idx & 63;
        s_t[f][r] = X[(size_t)(r0 + r) * DF + f];
    }
    __syncthreads();
    for (int idx = t; idx < DF * 128; idx += 512) {
        int f = idx >> 7, r = idx & 127;
        float x = s_t[f][r] * s_dv[r];
        __nv_bfloat16 h = __float2bfloat16(x);
        __nv_bfloat16 l = __float2bfloat16(x - __bfloat162float(h));
        g_X1h[(size_t)f * NN + r0 + r] = h;
        g_X1l[(size_t)f * NN + r0 + r] = l;
    }
    {
        const int base = blockIdx.x * ((NE * DF) / 128);
        for (int idx = t; idx < (NE * DF) / 128; idx += 512) g_Y[base + idx] = 0.f;
    }
#pragma unroll
    for (int i = 0; i < 4; ++i) {
        int e = 4 * (t + 512 * i);
        atomicAdd(&g_de[e + 0], acc_de[i].x);
        atomicAdd(&g_de[e + 1], acc_de[i].y);
        atomicAdd(&g_de[e + 2], acc_de[i].z);
        atomicAdd(&g_de[e + 3], acc_de[i].w);
    }
}

// ---------------- kernel 2: Y += H^T @ X1  (tile 64e x 64f, K split 2, KC=32, 3-stage) ----------------
__global__ __launch_bounds__(256) void k_gemm1() {
    constexpr int KC = 32;
    constexpr int NCH = 256;   // 8192 per K half / 32
    constexpr int AP = 72;     // bf16 pitch for [k][e] tile (64 data + 8 pad)
    constexpr int BPW = 20;    // u32 words per f-row (16 data + 4 pad)
    constexpr int ASTG = KC * AP;       // 2304 bf16 per stage per plane
    constexpr int BSTG = DF * BPW;      // 1280 words per stage per plane

    extern __shared__ char smem[];
    __nv_bfloat16* Ah = (__nv_bfloat16*)smem;          // [3][ASTG]
    __nv_bfloat16* Al = Ah + 3 * ASTG;                 // [3][ASTG]
    uint32_t* Bh = (uint32_t*)(Al + 3 * ASTG);         // [3][BSTG]
    uint32_t* Bl = Bh + 3 * BSTG;                      // [3][BSTG]

    const int t = threadIdx.x;
    const int e0 = blockIdx.x * 64;
    const int kbase0 = blockIdx.y * 8192;
    const int warp = t >> 5, lane = t & 31, g = lane >> 2, t4 = lane & 3;
    const int wm = (warp >> 2) * 32, wn = (warp & 3) * 16;  // 2m x 4n warps
    const int krow = ((lane >> 4) & 1) * 8 + (lane & 7);
    const int mcol8 = ((lane >> 3) & 1) * 8;

    float acc[2][2][4];
#pragma unroll
    for (int a = 0; a < 2; ++a)
#pragma unroll
        for (int b = 0; b < 2; ++b)
#pragma unroll
            for (int c = 0; c < 4; ++c) acc[a][b][c] = 0.f;

    // per-thread load coords
    const int ar = t >> 3, ac = t & 7;      // A: 32 rows x 8 16B-chunks (per plane)
    const int bf = t >> 2, bc = t & 3;      // B: 64 rows x 4 16B-chunks (per plane)

    auto load_chunk = [&](int ch, int st) {
        const int kb = kbase0 + ch * KC;
        cp16(Ah + st * ASTG + ar * AP + ac * 8, g_Hh + (size_t)(kb + ar) * NE + e0 + ac * 8);
        cp16(Al + st * ASTG + ar * AP + ac * 8, g_Hl + (size_t)(kb + ar) * NE + e0 + ac * 8);
        cp16(Bh + st * BSTG + bf * BPW + bc * 4, g_X1h + (size_t)bf * NN + kb + bc * 8);
        cp16(Bl + st * BSTG + bf * BPW + bc * 4, g_X1l + (size_t)bf * NN + kb + bc * 8);
    };

    auto compute = [&](int st) {
        const uint32_t abase_h = smem_u32(Ah + st * ASTG);
        const uint32_t abase_l = smem_u32(Al + st * ASTG);
        const uint32_t* BH = Bh + st * BSTG;
        const uint32_t* BL = Bl + st * BSTG;
#pragma unroll
        for (int s = 0; s < 2; ++s) {
            uint32_t ah[2][4], al[2][4], bh[2][2], bl[2][2];
#pragma unroll
            for (int mt = 0; mt < 2; ++mt) {
                uint32_t off = (uint32_t)(((s * 16 + krow) * AP + wm + mt * 16 + mcol8) * 2);
                ldsm4t(ah[mt], abase_h + off);
                ldsm4t(al[mt], abase_l + off);
            }
#pragma unroll
            for (int nt = 0; nt < 2; ++nt) {
                int n = wn + nt * 8 + g;
                bh[nt][0] = BH[n * BPW + s * 8 + t4];  bh[nt][1] = BH[n * BPW + s * 8 + t4 + 4];
                bl[nt][0] = BL[n * BPW + s * 8 + t4];  bl[nt][1] = BL[n * BPW + s * 8 + t4 + 4];
            }
#pragma unroll
            for (int mt = 0; mt < 2; ++mt)
#pragma unroll
                for (int nt = 0; nt < 2; ++nt) mma_bf16(acc[mt][nt], ah[mt], bh[nt]);
#pragma unroll
            for (int mt = 0; mt < 2; ++mt)
#pragma unroll
                for (int nt = 0; nt < 2; ++nt) mma_bf16(acc[mt][nt], ah[mt], bl[nt]);
#pragma unroll
            for (int mt = 0; mt < 2; ++mt)
#pragma unroll
                for (int nt = 0; nt < 2; ++nt) mma_bf16(acc[mt][nt], al[mt], bh[nt]);
        }
    };

    load_chunk(0, 0); cp_commit();
    load_chunk(1, 1); cp_commit();
#pragma unroll 1
    for (int ch = 0; ch < NCH; ++ch) {
        asm volatile("cp.async.wait_group 1;" ::: "memory");
        __syncthreads();
        if (ch + 2 < NCH) load_chunk(ch + 2, (ch + 2) % 3);
        cp_commit();  // uniform (possibly empty) group keeps accounting exact
        compute(ch % 3);
    }

    // atomic epilogue (K-split partials)
#pragma unroll
    for (int mt = 0; mt < 2; ++mt) {
        const int e = e0 + wm + mt * 16 + g;
#pragma unroll
        for (int nt = 0; nt < 2; ++nt) {
            const int n = wn + nt * 8 + 2 * t4;
            atomicAdd(&g_Y[(size_t)e * DF + n],           acc[mt][nt][0]);
            atomicAdd(&g_Y[(size_t)e * DF + n + 1],       acc[mt][nt][1]);
            atomicAdd(&g_Y[(size_t)(e + 8) * DF + n],     acc[mt][nt][2]);
            atomicAdd(&g_Y[(size_t)(e + 8) * DF + n + 1], acc[mt][nt][3]);
        }
    }
}

// ---------------- kernel 3: Y *= d_e, emit transposed bf16 hi/lo planes ----------------
__global__ __launch_bounds__(256) void k_scale_y() {
    const int idx = blockIdx.x * 256 + threadIdx.x;  // over NE*DF
    const int e = idx & (NE - 1);
    const int f = idx >> 13;
    float v = g_Y[(size_t)e * DF + f] * g_de[e];  // strided read (L2-resident)
    __nv_bfloat16 h = __float2bfloat16(v);
    __nv_bfloat16 l = __float2bfloat16(v - __bfloat162float(h));
    g_Yh[(size_t)f * NE + e] = h;  // coalesced write
    g_Yl[(size_t)f * NE + e] = l;
}

// ---------------- kernel 4: out = d_v * (H @ Y)  (tile 64v x 64f, KC=32, 3-stage) ----------------
__global__ __launch_bounds__(256) void k_gemm2(float* __restrict__ out) {
    constexpr int KC = 32;
    constexpr int NCH = 256;   // 8192 / 32
    constexpr int AP = 40;     // bf16 pitch for [v][k] tile (32 data + 8 pad)
    constexpr int BPW = 20;
    constexpr int ASTG = 64 * AP;       // 2560 bf16 per stage per plane
    constexpr int BSTG = DF * BPW;      // 1280 words

    extern __shared__ char smem[];
    __nv_bfloat16* Ah = (__nv_bfloat16*)smem;          // [3][ASTG]
    __nv_bfloat16* Al = Ah + 3 * ASTG;
    uint32_t* Bh = (uint32_t*)(Al + 3 * ASTG);         // [3][BSTG]
    uint32_t* Bl = Bh + 3 * BSTG;

    const int t = threadIdx.x;
    const int v0 = blockIdx.x * 64;
    const int warp = t >> 5, lane = t & 31, g = lane >> 2, t4 = lane & 3;
    const int wm = (warp >> 2) * 32, wn = (warp & 3) * 16;
    const int mrow = ((lane >> 3) & 1) * 8 + (lane & 7);
    const int kcol8 = ((lane >> 4) & 1) * 8;

    float acc[2][2][4];
#pragma unroll
    for (int a = 0; a < 2; ++a)
#pragma unroll
        for (int b = 0; b < 2; ++b)
#pragma unroll
            for (int c = 0; c < 4; ++c) acc[a][b][c] = 0.f;

    const int ar = t >> 2, ac = t & 3;      // A: 64 rows x 4 16B-chunks (per plane)
    const int bf = t >> 2, bc = t & 3;      // B: 64 rows x 4 chunks (per plane)

    auto load_chunk = [&](int ch, int st) {
        const int kb = ch * KC;
        cp16(Ah + st * ASTG + ar * AP + ac * 8, g_Hh + (size_t)(v0 + ar) * NE + kb + ac * 8);
        cp16(Al + st * ASTG + ar * AP + ac * 8, g_Hl + (size_t)(v0 + ar) * NE + kb + ac * 8);
        cp16(Bh + st * BSTG + bf * BPW + bc * 4, g_Yh + (size_t)bf * NE + kb + bc * 8);
        cp16(Bl + st * BSTG + bf * BPW + bc * 4, g_Yl + (size_t)bf * NE + kb + bc * 8);
    };

    auto compute = [&](int st) {
        const uint32_t abase_h = smem_u32(Ah + st * ASTG);
        const uint32_t abase_l = smem_u32(Al + st * ASTG);
        const uint32_t* BH = Bh + st * BSTG;
        const uint32_t* BL = Bl + st * BSTG;
#pragma unroll
        for (int s = 0; s < 2; ++s) {
            uint32_t ah[2][4], al[2][4], bh[2][2], bl[2][2];
#pragma unroll
            for (int mt = 0; mt < 2; ++mt) {
                uint32_t off = (uint32_t)(((wm + mt * 16 + mrow) * AP + s * 16 + kcol8) * 2);
                ldsm4(ah[mt], abase_h + off);
                ldsm4(al[mt], abase_l + off);
            }
#pragma unroll
            for (int nt = 0; nt < 2; ++nt) {
                int n = wn + nt * 8 + g;
                bh[nt][0] = BH[n * BPW + s * 8 + t4];  bh[nt][1] = BH[n * BPW + s * 8 + t4 + 4];
                bl[nt][0] = BL[n * BPW + s * 8 + t4];  bl[nt][1] = BL[n * BPW + s * 8 + t4 + 4];
            }
#pragma unroll
            for (int mt = 0; mt < 2; ++mt)
#pragma unroll
                for (int nt = 0; nt < 2; ++nt) mma_bf16(acc[mt][nt], ah[mt], bh[nt]);
#pragma unroll
            for (int mt = 0; mt < 2; ++mt)
#pragma unroll
                for (int nt = 0; nt < 2; ++nt) mma_bf16(acc[mt][nt], ah[mt], bl[nt]);
#pragma unroll
            for (int mt = 0; mt < 2; ++mt)
#pragma unroll
                for (int nt = 0; nt < 2; ++nt) mma_bf16(acc[mt][nt], al[mt], bh[nt]);
        }
    };

    load_chunk(0, 0); cp_commit();
    load_chunk(1, 1); cp_commit();
#pragma unroll 1
    for (int ch = 0; ch < NCH; ++ch) {
        asm volatile("cp.async.wait_group 1;" ::: "memory");
        __syncthreads();
        if (ch + 2 < NCH) load_chunk(ch + 2, (ch + 2) % 3);
        cp_commit();
        compute(ch % 3);
    }

    // direct store epilogue with d_v scaling
#pragma unroll
    for (int mt = 0; mt < 2; ++mt) {
        const int v = v0 + wm + mt * 16 + g;
        const float dlo = g_dv[v];
        const float dhi = g_dv[v + 8];
#pragma unroll
        for (int nt = 0; nt < 2; ++nt) {
            const int n = wn + nt * 8 + 2 * t4;
            float2 lo = make_float2(dlo * acc[mt][nt][0], dlo * acc[mt][nt][1]);
            float2 hi = make_float2(dhi * acc[mt][nt][2], dhi * acc[mt][nt][3]);
            *reinterpret_cast<float2*>(&out[(size_t)v * DF + n]) = lo;
            *reinterpret_cast<float2*>(&out[(size_t)(v + 8) * DF + n]) = hi;
        }
    }
}

// ---------------- launch ----------------
extern "C" void kernel_launch(void* const* d_in, const int* in_sizes, int n_in,
                              void* d_out, int out_size) {
    const float* H = (const float*)d_in[0];
    const float* X = (const float*)d_in[1];
    float* out = (float*)d_out;

    // dynamic smem: gemm1 = 3*2*2304*2 + 3*2*1280*4 = 27648 + 30720 = 58368 B
    //               gemm2 = 3*2*2560*2 + 3*2*1280*4 = 30720 + 30720 = 61440 B
    static bool attr_done = false;
    if (!attr_done) {
        cudaFuncSetAttribute(k_gemm1, cudaFuncAttributeMaxDynamicSharedMemorySize, 58368);
        cudaFuncSetAttribute(k_gemm2, cudaFuncAttributeMaxDynamicSharedMemorySize, 61440);
        attr_done = true;
    }

    void* de_ptr = nullptr;
    cudaGetSymbolAddress(&de_ptr, g_de);
    cudaMemsetAsync(de_ptr, 0, NE * sizeof(float));

    k_deg<<<128, 512>>>(H, X);
    dim3 grid1(NE / 64, 2);
    k_gemm1<<<grid1, 256, 58368>>>();
    k_scale_y<<<(NE * DF) / 256, 256>>>();
    k_gemm2<<<NN / 64, 256, 61440>>>(out);
}

// round 16
// speedup vs baseline: 1.6576x; 1.0121x over previous
#include <cuda_runtime.h>
#include <cuda_bf16.h>
#include <cstdint>
#include <cstddef>

#define NN 16384
#define NE 8192
#define DF 64

// scratch (device-global; no allocations allowed)
__device__ float g_dv[NN];
__device__ float g_de[NE];
__device__ float g_Y[NE * DF];
// pre-split bf16 hi/lo planes of H, native [node][edge] layout.
__device__ __nv_bfloat16 g_Hh[(size_t)NN * NE];
__device__ __nv_bfloat16 g_Hl[(size_t)NN * NE];
// B-operand planes, TRANSPOSED ([feature][node/edge]) for k-contiguous fragments.
__device__ __nv_bfloat16 g_X1h[DF * NN];
__device__ __nv_bfloat16 g_X1l[DF * NN];
__device__ __nv_bfloat16 g_Yh[DF * NE];
__device__ __nv_bfloat16 g_Yl[DF * NE];

// ---------------- helpers ----------------
__device__ __forceinline__ uint32_t smem_u32(const void* p) {
    return (uint32_t)__cvta_generic_to_shared(p);
}
__device__ __forceinline__ void cp16(void* s, const void* g) {
    asm volatile("cp.async.cg.shared.global [%0], [%1], 16;" :: "r"(smem_u32(s)), "l"(g));
}
__device__ __forceinline__ void cp_commit() {
    asm volatile("cp.async.commit_group;" ::: "memory");
}
__device__ __forceinline__ void mma_bf16(float* c, const uint32_t* a, const uint32_t* b) {
    asm volatile(
        "mma.sync.aligned.m16n8k16.row.col.f32.bf16.bf16.f32 "
        "{%0,%1,%2,%3}, {%4,%5,%6,%7}, {%8,%9}, {%0,%1,%2,%3};\n"
        : "+f"(c[0]), "+f"(c[1]), "+f"(c[2]), "+f"(c[3])
        : "r"(a[0]), "r"(a[1]), "r"(a[2]), "r"(a[3]), "r"(b[0]), "r"(b[1]));
}
__device__ __forceinline__ void ldsm4(uint32_t* r, uint32_t a) {
    asm volatile("ldmatrix.sync.aligned.m8n8.x4.shared.b16 {%0,%1,%2,%3}, [%4];"
                 : "=r"(r[0]), "=r"(r[1]), "=r"(r[2]), "=r"(r[3]) : "r"(a));
}
__device__ __forceinline__ void ldsm4t(uint32_t* r, uint32_t a) {
    asm volatile("ldmatrix.sync.aligned.m8n8.x4.trans.shared.b16 {%0,%1,%2,%3}, [%4];"
                 : "=r"(r[0]), "=r"(r[1]), "=r"(r[2]), "=r"(r[3]) : "r"(a));
}
// split two consecutive f32 into packed bf16 hi pair + lo pair (x0 in low half)
__device__ __forceinline__ void bf16x2_split(float x0, float x1, uint32_t& hi, uint32_t& lo) {
    asm("cvt.rn.bf16x2.f32 %0, %1, %2;" : "=r"(hi) : "f"(x1), "f"(x0));
    float h0 = __uint_as_float(hi << 16);          // bf16->f32 exact
    float h1 = __uint_as_float(hi & 0xffff0000u);
    asm("cvt.rn.bf16x2.f32 %0, %1, %2;" : "=r"(lo) : "f"(x1 - h1), "f"(x0 - h0));
}

// ---------------- kernel 1: d_v, d_e partials, H planes, X1 planes, zero Y ----------------
__global__ __launch_bounds__(512) void k_deg(const float* __restrict__ H,
                                             const float* __restrict__ X) {
    const int t = threadIdx.x;
    const int r0 = blockIdx.x * 128;
    const int wid = t >> 5, lane = t & 31;
    __shared__ float s_wpart[128][16];
    __shared__ float s_dv[128];
    __shared__ float s_t[64][133];

    float4 acc_de[4];
#pragma unroll
    for (int i = 0; i < 4; ++i) acc_de[i] = make_float4(0.f, 0.f, 0.f, 0.f);

    for (int r = 0; r < 128; ++r) {
        const float4* row = reinterpret_cast<const float4*>(H + (size_t)(r0 + r) * NE);
        uint2* dh = reinterpret_cast<uint2*>(g_Hh + (size_t)(r0 + r) * NE);
        uint2* dl = reinterpret_cast<uint2*>(g_Hl + (size_t)(r0 + r) * NE);
        float rs = 0.f;
#pragma unroll
        for (int i = 0; i < 4; ++i) {
            float4 v = row[t + 512 * i];
            acc_de[i].x += v.x; acc_de[i].y += v.y;
            acc_de[i].z += v.z; acc_de[i].w += v.w;
            rs += (v.x + v.y) + (v.z + v.w);
            uint32_t h0, l0, h1, l1;
            bf16x2_split(v.x, v.y, h0, l0);
            bf16x2_split(v.z, v.w, h1, l1);
            dh[t + 512 * i] = make_uint2(h0, h1);
            dl[t + 512 * i] = make_uint2(l0, l1);
        }
#pragma unroll
        for (int o = 16; o; o >>= 1) rs += __shfl_down_sync(0xffffffffu, rs, o);
        if (lane == 0) s_wpart[r][wid] = rs;
    }
    __syncthreads();
    if (t < 128) {
        float s = 0.f;
#pragma unroll
        for (int w = 0; w < 16; ++w) s += s_wpart[t][w];
        g_dv[r0 + t] = s;
        s_dv[t] = s;
    }
    __syncthreads();
    for (int idx = t; idx < 128 * DF; idx += 512) {
        int r = idx >> 6, f = idx & 63;
        s_t[f][r] = X[(size_t)(r0 + r) * DF + f];
    }
    __syncthreads();
    for (int idx = t; idx < DF * 128; idx += 512) {
        int f = idx >> 7, r = idx & 127;
        float x = s_t[f][r] * s_dv[r];
        __nv_bfloat16 h = __float2bfloat16(x);
        __nv_bfloat16 l = __float2bfloat16(x - __bfloat162float(h));
        g_X1h[(size_t)f * NN + r0 + r] = h;
        g_X1l[(size_t)f * NN + r0 + r] = l;
    }
    {
        const int base = blockIdx.x * ((NE * DF) / 128);
        for (int idx = t; idx < (NE * DF) / 128; idx += 512) g_Y[base + idx] = 0.f;
    }
#pragma unroll
    for (int i = 0; i < 4; ++i) {
        int e = 4 * (t + 512 * i);
        atomicAdd(&g_de[e + 0], acc_de[i].x);
        atomicAdd(&g_de[e + 1], acc_de[i].y);
        atomicAdd(&g_de[e + 2], acc_de[i].z);
        atomicAdd(&g_de[e + 3], acc_de[i].w);
    }
}

// ---------------- kernel 2: Y += H^T @ X1  (tile 64e x 64f, K split 2, KC=32, 4-stage) ----------------
// Warp grid 2m x 2n x 2k-split: A and B fragments each read only 2x (was 4x/2x).
__global__ __launch_bounds__(256) void k_gemm1() {
    constexpr int KC = 32;
    constexpr int NCH = 256;
    constexpr int NS = 4;
    constexpr int AP = 72;
    constexpr int BPW = 20;
    constexpr int ASTG = KC * AP;       // 2304 bf16 per stage per plane
    constexpr int BSTG = DF * BPW;      // 1280 words per stage per plane

    extern __shared__ char smem[];
    __nv_bfloat16* Ah = (__nv_bfloat16*)smem;
    __nv_bfloat16* Al = Ah + NS * ASTG;
    uint32_t* Bh = (uint32_t*)(Al + NS * ASTG);
    uint32_t* Bl = Bh + NS * BSTG;

    const int t = threadIdx.x;
    const int e0 = blockIdx.x * 64;
    const int kbase0 = blockIdx.y * 8192;
    const int warp = t >> 5, lane = t & 31, g = lane >> 2, t4 = lane & 3;
    const int wm = ((warp >> 2) & 1) * 32;   // m-group
    const int wn = ((warp >> 1) & 1) * 32;   // n-group
    const int sg = warp & 1;                 // k-half within chunk
    const int ks = sg * 16, ksw = sg * 8;
    const int krow = ((lane >> 4) & 1) * 8 + (lane & 7);
    const int mcol8 = ((lane >> 3) & 1) * 8;

    float acc[2][4][4];
#pragma unroll
    for (int a = 0; a < 2; ++a)
#pragma unroll
        for (int b = 0; b < 4; ++b)
#pragma unroll
            for (int c = 0; c < 4; ++c) acc[a][b][c] = 0.f;

    const int ar = t >> 3, ac = t & 7;
    const int bfr = t >> 2, bc = t & 3;

    auto load_chunk = [&](int ch, int st) {
        const int kb = kbase0 + ch * KC;
        cp16(Ah + st * ASTG + ar * AP + ac * 8, g_Hh + (size_t)(kb + ar) * NE + e0 + ac * 8);
        cp16(Al + st * ASTG + ar * AP + ac * 8, g_Hl + (size_t)(kb + ar) * NE + e0 + ac * 8);
        cp16(Bh + st * BSTG + bfr * BPW + bc * 4, g_X1h + (size_t)bfr * NN + kb + bc * 8);
        cp16(Bl + st * BSTG + bfr * BPW + bc * 4, g_X1l + (size_t)bfr * NN + kb + bc * 8);
    };

    auto compute = [&](int st) {
        const uint32_t abase_h = smem_u32(Ah + st * ASTG);
        const uint32_t abase_l = smem_u32(Al + st * ASTG);
        const uint32_t* BH = Bh + st * BSTG;
        const uint32_t* BL = Bl + st * BSTG;
        uint32_t ah[2][4], al[2][4], bh[4][2], bl[4][2];
#pragma unroll
        for (int mt = 0; mt < 2; ++mt) {
            uint32_t off = (uint32_t)(((ks + krow) * AP + wm + mt * 16 + mcol8) * 2);
            ldsm4t(ah[mt], abase_h + off);
            ldsm4t(al[mt], abase_l + off);
        }
#pragma unroll
        for (int nt = 0; nt < 4; ++nt) {
            int n = wn + nt * 8 + g;
            bh[nt][0] = BH[n * BPW + ksw + t4];  bh[nt][1] = BH[n * BPW + ksw + t4 + 4];
            bl[nt][0] = BL[n * BPW + ksw + t4];  bl[nt][1] = BL[n * BPW + ksw + t4 + 4];
        }
#pragma unroll
        for (int mt = 0; mt < 2; ++mt)
#pragma unroll
            for (int nt = 0; nt < 4; ++nt) mma_bf16(acc[mt][nt], ah[mt], bh[nt]);
#pragma unroll
        for (int mt = 0; mt < 2; ++mt)
#pragma unroll
            for (int nt = 0; nt < 4; ++nt) mma_bf16(acc[mt][nt], ah[mt], bl[nt]);
#pragma unroll
        for (int mt = 0; mt < 2; ++mt)
#pragma unroll
            for (int nt = 0; nt < 4; ++nt) mma_bf16(acc[mt][nt], al[mt], bh[nt]);
    };

    load_chunk(0, 0); cp_commit();
    load_chunk(1, 1); cp_commit();
    load_chunk(2, 2); cp_commit();
#pragma unroll 1
    for (int ch = 0; ch < NCH; ++ch) {
        asm volatile("cp.async.wait_group 2;" ::: "memory");
        __syncthreads();
        if (ch + 3 < NCH) load_chunk(ch + 3, (ch + 3) & 3);
        cp_commit();
        compute(ch & 3);
    }

    // atomic epilogue (sums K-split halves, warp k-halves, and grid.y halves)
#pragma unroll
    for (int mt = 0; mt < 2; ++mt) {
        const int e = e0 + wm + mt * 16 + g;
#pragma unroll
        for (int nt = 0; nt < 4; ++nt) {
            const int n = wn + nt * 8 + 2 * t4;
            atomicAdd(&g_Y[(size_t)e * DF + n],           acc[mt][nt][0]);
            atomicAdd(&g_Y[(size_t)e * DF + n + 1],       acc[mt][nt][1]);
            atomicAdd(&g_Y[(size_t)(e + 8) * DF + n],     acc[mt][nt][2]);
            atomicAdd(&g_Y[(size_t)(e + 8) * DF + n + 1], acc[mt][nt][3]);
        }
    }
}

// ---------------- kernel 3: Y *= d_e, emit transposed bf16 hi/lo planes ----------------
__global__ __launch_bounds__(256) void k_scale_y() {
    const int idx = blockIdx.x * 256 + threadIdx.x;
    const int e = idx & (NE - 1);
    const int f = idx >> 13;
    float v = g_Y[(size_t)e * DF + f] * g_de[e];
    __nv_bfloat16 h = __float2bfloat16(v);
    __nv_bfloat16 l = __float2bfloat16(v - __bfloat162float(h));
    g_Yh[(size_t)f * NE + e] = h;
    g_Yl[(size_t)f * NE + e] = l;
}

// ---------------- kernel 4: out = d_v * (H @ Y)  (tile 64v x 64f, KC=32, 4-stage) ----------------
__global__ __launch_bounds__(256) void k_gemm2(float* __restrict__ out) {
    constexpr int KC = 32;
    constexpr int NCH = 256;
    constexpr int NS = 4;
    constexpr int AP = 40;
    constexpr int BPW = 20;
    constexpr int ASTG = 64 * AP;       // 2560 bf16 per stage per plane
    constexpr int BSTG = DF * BPW;      // 1280 words
    constexpr int RP = 66;              // reduction buffer pitch (f32)

    extern __shared__ char smem[];
    __nv_bfloat16* Ah = (__nv_bfloat16*)smem;
    __nv_bfloat16* Al = Ah + NS * ASTG;
    uint32_t* Bh = (uint32_t*)(Al + NS * ASTG);
    uint32_t* Bl = Bh + NS * BSTG;

    const int t = threadIdx.x;
    const int v0 = blockIdx.x * 64;
    const int warp = t >> 5, lane = t & 31, g = lane >> 2, t4 = lane & 3;
    const int wm = ((warp >> 2) & 1) * 32;
    const int wn = ((warp >> 1) & 1) * 32;
    const int sg = warp & 1;
    const int ks = sg * 16, ksw = sg * 8;
    const int mrow = ((lane >> 3) & 1) * 8 + (lane & 7);
    const int kcol8 = ((lane >> 4) & 1) * 8;

    float acc[2][4][4];
#pragma unroll
    for (int a = 0; a < 2; ++a)
#pragma unroll
        for (int b = 0; b < 4; ++b)
#pragma unroll
            for (int c = 0; c < 4; ++c) acc[a][b][c] = 0.f;

    const int ar = t >> 2, ac = t & 3;
    const int bfr = t >> 2, bc = t & 3;

    auto load_chunk = [&](int ch, int st) {
        const int kb = ch * KC;
        cp16(Ah + st * ASTG + ar * AP + ac * 8, g_Hh + (size_t)(v0 + ar) * NE + kb + ac * 8);
        cp16(Al + st * ASTG + ar * AP + ac * 8, g_Hl + (size_t)(v0 + ar) * NE + kb + ac * 8);
        cp16(Bh + st * BSTG + bfr * BPW + bc * 4, g_Yh + (size_t)bfr * NE + kb + bc * 8);
        cp16(Bl + st * BSTG + bfr * BPW + bc * 4, g_Yl + (size_t)bfr * NE + kb + bc * 8);
    };

    auto compute = [&](int st) {
        const uint32_t abase_h = smem_u32(Ah + st * ASTG);
        const uint32_t abase_l = smem_u32(Al + st * ASTG);
        const uint32_t* BH = Bh + st * BSTG;
        const uint32_t* BL = Bl + st * BSTG;
        uint32_t ah[2][4], al[2][4], bh[4][2], bl[4][2];
#pragma unroll
        for (int mt = 0; mt < 2; ++mt) {
            uint32_t off = (uint32_t)(((wm + mt * 16 + mrow) * AP + ks + kcol8) * 2);
            ldsm4(ah[mt], abase_h + off);
            ldsm4(al[mt], abase_l + off);
        }
#pragma unroll
        for (int nt = 0; nt < 4; ++nt) {
            int n = wn + nt * 8 + g;
            bh[nt][0] = BH[n * BPW + ksw + t4];  bh[nt][1] = BH[n * BPW + ksw + t4 + 4];
            bl[nt][0] = BL[n * BPW + ksw + t4];  bl[nt][1] = BL[n * BPW + ksw + t4 + 4];
        }
#pragma unroll
        for (int mt = 0; mt < 2; ++mt)
#pragma unroll
            for (int nt = 0; nt < 4; ++nt) mma_bf16(acc[mt][nt], ah[mt], bh[nt]);
#pragma unroll
        for (int mt = 0; mt < 2; ++mt)
#pragma unroll
            for (int nt = 0; nt < 4; ++nt) mma_bf16(acc[mt][nt], ah[mt], bl[nt]);
#pragma unroll
        for (int mt = 0; mt < 2; ++mt)
#pragma unroll
            for (int nt = 0; nt < 4; ++nt) mma_bf16(acc[mt][nt], al[mt], bh[nt]);
    };

    load_chunk(0, 0); cp_commit();
    load_chunk(1, 1); cp_commit();
    load_chunk(2, 2); cp_commit();
#pragma unroll 1
    for (int ch = 0; ch < NCH; ++ch) {
        asm volatile("cp.async.wait_group 2;" ::: "memory");
        __syncthreads();
        if (ch + 3 < NCH) load_chunk(ch + 3, (ch + 3) & 3);
        cp_commit();
        compute(ch & 3);
    }

    // k-split reduction via smem (stage buffers are dead now), then scaled store
    __syncthreads();
    float* red = (float*)smem;   // [64][RP]
    if (sg == 1) {
#pragma unroll
        for (int mt = 0; mt < 2; ++mt) {
            const int r = wm + mt * 16 + g;
#pragma unroll
            for (int nt = 0; nt < 4; ++nt) {
                const int c = wn + nt * 8 + 2 * t4;
                red[r * RP + c]           = acc[mt][nt][0];
                red[r * RP + c + 1]       = acc[mt][nt][1];
                red[(r + 8) * RP + c]     = acc[mt][nt][2];
                red[(r + 8) * RP + c + 1] = acc[mt][nt][3];
            }
        }
    }
    __syncthreads();
    if (sg == 0) {
#pragma unroll
        for (int mt = 0; mt < 2; ++mt) {
            const int r = wm + mt * 16 + g;
            const int v = v0 + r;
            const float dlo = g_dv[v];
            const float dhi = g_dv[v + 8];
#pragma unroll
            for (int nt = 0; nt < 4; ++nt) {
                const int c = wn + nt * 8 + 2 * t4;
                float2 lo = make_float2(dlo * (acc[mt][nt][0] + red[r * RP + c]),
                                        dlo * (acc[mt][nt][1] + red[r * RP + c + 1]));
                float2 hi = make_float2(dhi * (acc[mt][nt][2] + red[(r + 8) * RP + c]),
                                        dhi * (acc[mt][nt][3] + red[(r + 8) * RP + c + 1]));
                *reinterpret_cast<float2*>(&out[(size_t)v * DF + c]) = lo;
                *reinterpret_cast<float2*>(&out[(size_t)(v + 8) * DF + c]) = hi;
            }
        }
    }
}

// ---------------- launch ----------------
extern "C" void kernel_launch(void* const* d_in, const int* in_sizes, int n_in,
                              void* d_out, int out_size) {
    const float* H = (const float*)d_in[0];
    const float* X = (const float*)d_in[1];
    float* out = (float*)d_out;

    // dynamic smem: gemm1 = 4*(2*2304*2 + 2*1280*4) = 77824 B
    //               gemm2 = 4*(2*2560*2 + 2*1280*4) = 81920 B
    static bool attr_done = false;
    if (!attr_done) {
        cudaFuncSetAttribute(k_gemm1, cudaFuncAttributeMaxDynamicSharedMemorySize, 77824);
        cudaFuncSetAttribute(k_gemm2, cudaFuncAttributeMaxDynamicSharedMemorySize, 81920);
        attr_done = true;
    }

    void* de_ptr = nullptr;
    cudaGetSymbolAddress(&de_ptr, g_de);
    cudaMemsetAsync(de_ptr, 0, NE * sizeof(float));

    k_deg<<<128, 512>>>(H, X);
    dim3 grid1(NE / 64, 2);
    k_gemm1<<<grid1, 256, 77824>>>();
    k_scale_y<<<(NE * DF) / 256, 256>>>();
    k_gemm2<<<NN / 64, 256, 81920>>>(out);
}

// round 17
// speedup vs baseline: 1.8214x; 1.0988x over previous
#include <cuda_runtime.h>
#include <cuda_bf16.h>
#include <cstdint>
#include <cstddef>

#define NN 16384
#define NE 8192
#define DF 64

// scratch (device-global; no allocations allowed)
__device__ float g_dv[NN];
__device__ float g_de[NE];
__device__ float g_Y[NE * DF];
// pre-split bf16 hi/lo planes of H, native [node][edge] layout.
__device__ __nv_bfloat16 g_Hh[(size_t)NN * NE];
__device__ __nv_bfloat16 g_Hl[(size_t)NN * NE];
// B-operand planes, TRANSPOSED ([feature][node/edge]) for k-contiguous fragments.
__device__ __nv_bfloat16 g_X1h[DF * NN];
__device__ __nv_bfloat16 g_X1l[DF * NN];
__device__ __nv_bfloat16 g_Yh[DF * NE];
__device__ __nv_bfloat16 g_Yl[DF * NE];

// ---------------- helpers ----------------
__device__ __forceinline__ uint32_t smem_u32(const void* p) {
    return (uint32_t)__cvta_generic_to_shared(p);
}
__device__ __forceinline__ void cp16(void* s, const void* g) {
    asm volatile("cp.async.cg.shared.global [%0], [%1], 16;" :: "r"(smem_u32(s)), "l"(g));
}
__device__ __forceinline__ void cp_commit() {
    asm volatile("cp.async.commit_group;" ::: "memory");
}
__device__ __forceinline__ void mma_bf16(float* c, const uint32_t* a, const uint32_t* b) {
    asm volatile(
        "mma.sync.aligned.m16n8k16.row.col.f32.bf16.bf16.f32 "
        "{%0,%1,%2,%3}, {%4,%5,%6,%7}, {%8,%9}, {%0,%1,%2,%3};\n"
        : "+f"(c[0]), "+f"(c[1]), "+f"(c[2]), "+f"(c[3])
        : "r"(a[0]), "r"(a[1]), "r"(a[2]), "r"(a[3]), "r"(b[0]), "r"(b[1]));
}
__device__ __forceinline__ void ldsm4(uint32_t* r, uint32_t a) {
    asm volatile("ldmatrix.sync.aligned.m8n8.x4.shared.b16 {%0,%1,%2,%3}, [%4];"
                 : "=r"(r[0]), "=r"(r[1]), "=r"(r[2]), "=r"(r[3]) : "r"(a));
}
__device__ __forceinline__ void ldsm4t(uint32_t* r, uint32_t a) {
    asm volatile("ldmatrix.sync.aligned.m8n8.x4.trans.shared.b16 {%0,%1,%2,%3}, [%4];"
                 : "=r"(r[0]), "=r"(r[1]), "=r"(r[2]), "=r"(r[3]) : "r"(a));
}
// split two consecutive f32 into packed bf16 hi pair + lo pair (x0 in low half)
__device__ __forceinline__ void bf16x2_split(float x0, float x1, uint32_t& hi, uint32_t& lo) {
    asm("cvt.rn.bf16x2.f32 %0, %1, %2;" : "=r"(hi) : "f"(x1), "f"(x0));
    float h0 = __uint_as_float(hi << 16);          // bf16->f32 exact
    float h1 = __uint_as_float(hi & 0xffff0000u);
    asm("cvt.rn.bf16x2.f32 %0, %1, %2;" : "=r"(lo) : "f"(x1 - h1), "f"(x0 - h0));
}

// ---------------- kernel 1: d_v, d_e partials, H planes, X1 planes, zero Y ----------------
__global__ __launch_bounds__(512) void k_deg(const float* __restrict__ H,
                                             const float* __restrict__ X) {
    const int t = threadIdx.x;
    const int r0 = blockIdx.x * 128;
    const int wid = t >> 5, lane = t & 31;
    __shared__ float s_wpart[128][16];
    __shared__ float s_dv[128];
    __shared__ float s_t[64][133];

    float4 acc_de[4];
#pragma unroll
    for (int i = 0; i < 4; ++i) acc_de[i] = make_float4(0.f, 0.f, 0.f, 0.f);

    for (int r = 0; r < 128; ++r) {
        const float4* row = reinterpret_cast<const float4*>(H + (size_t)(r0 + r) * NE);
        uint2* dh = reinterpret_cast<uint2*>(g_Hh + (size_t)(r0 + r) * NE);
        uint2* dl = reinterpret_cast<uint2*>(g_Hl + (size_t)(r0 + r) * NE);
        float rs = 0.f;
#pragma unroll
        for (int i = 0; i < 4; ++i) {
            float4 v = row[t + 512 * i];
            acc_de[i].x += v.x; acc_de[i].y += v.y;
            acc_de[i].z += v.z; acc_de[i].w += v.w;
            rs += (v.x + v.y) + (v.z + v.w);
            uint32_t h0, l0, h1, l1;
            bf16x2_split(v.x, v.y, h0, l0);
            bf16x2_split(v.z, v.w, h1, l1);
            dh[t + 512 * i] = make_uint2(h0, h1);
            dl[t + 512 * i] = make_uint2(l0, l1);
        }
#pragma unroll
        for (int o = 16; o; o >>= 1) rs += __shfl_down_sync(0xffffffffu, rs, o);
        if (lane == 0) s_wpart[r][wid] = rs;
    }
    __syncthreads();
    if (t < 128) {
        float s = 0.f;
#pragma unroll
        for (int w = 0; w < 16; ++w) s += s_wpart[t][w];
        g_dv[r0 + t] = s;
        s_dv[t] = s;
    }
    __syncthreads();
    for (int idx = t; idx < 128 * DF; idx += 512) {
        int r = idx >> 6, f = idx & 63;
        s_t[f][r] = X[(size_t)(r0 + r) * DF + f];
    }
    __syncthreads();
    for (int idx = t; idx < DF * 128; idx += 512) {
        int f = idx >> 7, r = idx & 127;
        float x = s_t[f][r] * s_dv[r];
        __nv_bfloat16 h = __float2bfloat16(x);
        __nv_bfloat16 l = __float2bfloat16(x - __bfloat162float(h));
        g_X1h[(size_t)f * NN + r0 + r] = h;
        g_X1l[(size_t)f * NN + r0 + r] = l;
    }
    {
        const int base = blockIdx.x * ((NE * DF) / 128);
        for (int idx = t; idx < (NE * DF) / 128; idx += 512) g_Y[base + idx] = 0.f;
    }
#pragma unroll
    for (int i = 0; i < 4; ++i) {
        int e = 4 * (t + 512 * i);
        atomicAdd(&g_de[e + 0], acc_de[i].x);
        atomicAdd(&g_de[e + 1], acc_de[i].y);
        atomicAdd(&g_de[e + 2], acc_de[i].z);
        atomicAdd(&g_de[e + 3], acc_de[i].w);
    }
}

// ---------------- kernel 2: Y += H^T @ X1  (tile 128e x 64f, K split 2, KC=64, NS=4, 512 thr) ----------------
// Warp grid 4m x 2n x 2k-split.
__global__ __launch_bounds__(512) void k_gemm1() {
    constexpr int KC = 64;
    constexpr int NCH = 128;            // 8192 nodes per K half / 64
    constexpr int NS = 4;
    constexpr int AP = 136;             // [k][e] pitch: 128 e + 8 pad (272B rows, 17 units -> ldsm4t ok)
    constexpr int BPW = 36;             // words per f-row: 32 data + 4 pad
    constexpr int ASTG = KC * AP;       // 8704 bf16 per stage per plane
    constexpr int BSTG = DF * BPW;      // 2304 words per stage per plane

    extern __shared__ char smem[];
    __nv_bfloat16* Ah = (__nv_bfloat16*)smem;
    __nv_bfloat16* Al = Ah + NS * ASTG;
    uint32_t* Bh = (uint32_t*)(Al + NS * ASTG);
    uint32_t* Bl = Bh + NS * BSTG;

    const int t = threadIdx.x;
    const int e0 = blockIdx.x * 128;
    const int kbase0 = blockIdx.y * 8192;
    const int warp = t >> 5, lane = t & 31, g = lane >> 2, t4 = lane & 3;
    const int wm = (warp >> 2) * 32;         // 4 m-groups over 128 e
    const int wn = ((warp >> 1) & 1) * 32;   // 2 n-groups
    const int sg = warp & 1;                 // k-half (32) within KC=64
    const int krow = ((lane >> 4) & 1) * 8 + (lane & 7);
    const int mcol8 = ((lane >> 3) & 1) * 8;

    float acc[2][4][4];
#pragma unroll
    for (int a = 0; a < 2; ++a)
#pragma unroll
        for (int b = 0; b < 4; ++b)
#pragma unroll
            for (int c = 0; c < 4; ++c) acc[a][b][c] = 0.f;

    // loads: A 64 rows x 16 chunks/plane (2 per thread), B 64 rows x 8 chunks (1 per thread)
    const int ar = t >> 3, ac = t & 7;
    const int bfr = t >> 3, bc2 = t & 7;

    auto load_chunk = [&](int ch, int st) {
        const int kb = kbase0 + ch * KC;
        cp16(Ah + st * ASTG + ar * AP + ac * 8,       g_Hh + (size_t)(kb + ar) * NE + e0 + ac * 8);
        cp16(Ah + st * ASTG + ar * AP + (ac + 8) * 8, g_Hh + (size_t)(kb + ar) * NE + e0 + (ac + 8) * 8);
        cp16(Al + st * ASTG + ar * AP + ac * 8,       g_Hl + (size_t)(kb + ar) * NE + e0 + ac * 8);
        cp16(Al + st * ASTG + ar * AP + (ac + 8) * 8, g_Hl + (size_t)(kb + ar) * NE + e0 + (ac + 8) * 8);
        cp16(Bh + st * BSTG + bfr * BPW + bc2 * 4, g_X1h + (size_t)bfr * NN + kb + bc2 * 8);
        cp16(Bl + st * BSTG + bfr * BPW + bc2 * 4, g_X1l + (size_t)bfr * NN + kb + bc2 * 8);
    };

    auto compute = [&](int st) {
        const uint32_t abase_h = smem_u32(Ah + st * ASTG);
        const uint32_t abase_l = smem_u32(Al + st * ASTG);
        const uint32_t* BH = Bh + st * BSTG;
        const uint32_t* BL = Bl + st * BSTG;
#pragma unroll
        for (int kb = 0; kb < 2; ++kb) {
            const int k0 = sg * 32 + kb * 16;
            uint32_t ah[2][4], al[2][4], bh[4][2], bl[4][2];
#pragma unroll
            for (int mt = 0; mt < 2; ++mt) {
                uint32_t off = (uint32_t)(((k0 + krow) * AP + wm + mt * 16 + mcol8) * 2);
                ldsm4t(ah[mt], abase_h + off);
                ldsm4t(al[mt], abase_l + off);
            }
#pragma unroll
            for (int nt = 0; nt < 4; ++nt) {
                int n = wn + nt * 8 + g;
                int w0 = n * BPW + sg * 16 + kb * 8 + t4;
                bh[nt][0] = BH[w0];  bh[nt][1] = BH[w0 + 4];
                bl[nt][0] = BL[w0];  bl[nt][1] = BL[w0 + 4];
            }
#pragma unroll
            for (int mt = 0; mt < 2; ++mt)
#pragma unroll
                for (int nt = 0; nt < 4; ++nt) mma_bf16(acc[mt][nt], ah[mt], bh[nt]);
#pragma unroll
            for (int mt = 0; mt < 2; ++mt)
#pragma unroll
                for (int nt = 0; nt < 4; ++nt) mma_bf16(acc[mt][nt], ah[mt], bl[nt]);
#pragma unroll
            for (int mt = 0; mt < 2; ++mt)
#pragma unroll
                for (int nt = 0; nt < 4; ++nt) mma_bf16(acc[mt][nt], al[mt], bh[nt]);
        }
    };

    load_chunk(0, 0); cp_commit();
    load_chunk(1, 1); cp_commit();
    load_chunk(2, 2); cp_commit();
#pragma unroll 1
    for (int ch = 0; ch < NCH; ++ch) {
        asm volatile("cp.async.wait_group 2;" ::: "memory");
        __syncthreads();
        if (ch + 3 < NCH) load_chunk(ch + 3, (ch + 3) & 3);
        cp_commit();
        compute(ch & 3);
    }

    // atomic epilogue (sums warp k-halves and grid.y halves)
#pragma unroll
    for (int mt = 0; mt < 2; ++mt) {
        const int e = e0 + wm + mt * 16 + g;
#pragma unroll
        for (int nt = 0; nt < 4; ++nt) {
            const int n = wn + nt * 8 + 2 * t4;
            atomicAdd(&g_Y[(size_t)e * DF + n],           acc[mt][nt][0]);
            atomicAdd(&g_Y[(size_t)e * DF + n + 1],       acc[mt][nt][1]);
            atomicAdd(&g_Y[(size_t)(e + 8) * DF + n],     acc[mt][nt][2]);
            atomicAdd(&g_Y[(size_t)(e + 8) * DF + n + 1], acc[mt][nt][3]);
        }
    }
}

// ---------------- kernel 3: Y *= d_e, emit transposed bf16 hi/lo planes ----------------
__global__ __launch_bounds__(256) void k_scale_y() {
    const int idx = blockIdx.x * 256 + threadIdx.x;
    const int e = idx & (NE - 1);
    const int f = idx >> 13;
    float v = g_Y[(size_t)e * DF + f] * g_de[e];
    __nv_bfloat16 h = __float2bfloat16(v);
    __nv_bfloat16 l = __float2bfloat16(v - __bfloat162float(h));
    g_Yh[(size_t)f * NE + e] = h;
    g_Yl[(size_t)f * NE + e] = l;
}

// ---------------- kernel 4: out = d_v * (H @ Y)  (tile 128v x 64f, KC=64, NS=4, 512 thr) ----------------
__global__ __launch_bounds__(512) void k_gemm2(float* __restrict__ out) {
    constexpr int KC = 64;
    constexpr int NCH = 128;            // 8192 / 64
    constexpr int NS = 4;
    constexpr int AP = 72;              // [v][k] pitch: 64 k + 8 pad (144B rows, 9 units -> ldsm ok)
    constexpr int BPW = 36;
    constexpr int ASTG = 128 * AP;      // 9216 bf16 per stage per plane
    constexpr int BSTG = DF * BPW;      // 2304 words
    constexpr int RP = 66;              // reduction buffer pitch (f32)

    extern __shared__ char smem[];
    __nv_bfloat16* Ah = (__nv_bfloat16*)smem;
    __nv_bfloat16* Al = Ah + NS * ASTG;
    uint32_t* Bh = (uint32_t*)(Al + NS * ASTG);
    uint32_t* Bl = Bh + NS * BSTG;

    const int t = threadIdx.x;
    const int v0 = blockIdx.x * 128;
    const int warp = t >> 5, lane = t & 31, g = lane >> 2, t4 = lane & 3;
    const int wm = (warp >> 2) * 32;         // 4 m-groups over 128 v
    const int wn = ((warp >> 1) & 1) * 32;
    const int sg = warp & 1;
    const int mrow = ((lane >> 3) & 1) * 8 + (lane & 7);
    const int kcol8 = ((lane >> 4) & 1) * 8;

    float acc[2][4][4];
#pragma unroll
    for (int a = 0; a < 2; ++a)
#pragma unroll
        for (int b = 0; b < 4; ++b)
#pragma unroll
            for (int c = 0; c < 4; ++c) acc[a][b][c] = 0.f;

    // loads: A 128 rows x 8 chunks/plane (2 per thread), B 64 rows x 8 chunks (1 per thread)
    const int ar = t >> 2, ac = t & 3;
    const int bfr = t >> 3, bc2 = t & 7;

    auto load_chunk = [&](int ch, int st) {
        const int kb = ch * KC;
        cp16(Ah + st * ASTG + ar * AP + ac * 8,       g_Hh + (size_t)(v0 + ar) * NE + kb + ac * 8);
        cp16(Ah + st * ASTG + ar * AP + (ac + 4) * 8, g_Hh + (size_t)(v0 + ar) * NE + kb + (ac + 4) * 8);
        cp16(Al + st * ASTG + ar * AP + ac * 8,       g_Hl + (size_t)(v0 + ar) * NE + kb + ac * 8);
        cp16(Al + st * ASTG + ar * AP + (ac + 4) * 8, g_Hl + (size_t)(v0 + ar) * NE + kb + (ac + 4) * 8);
        cp16(Bh + st * BSTG + bfr * BPW + bc2 * 4, g_Yh + (size_t)bfr * NE + kb + bc2 * 8);
        cp16(Bl + st * BSTG + bfr * BPW + bc2 * 4, g_Yl + (size_t)bfr * NE + kb + bc2 * 8);
    };

    auto compute = [&](int st) {
        const uint32_t abase_h = smem_u32(Ah + st * ASTG);
        const uint32_t abase_l = smem_u32(Al + st * ASTG);
        const uint32_t* BH = Bh + st * BSTG;
        const uint32_t* BL = Bl + st * BSTG;
#pragma unroll
        for (int kb = 0; kb < 2; ++kb) {
            const int k0 = sg * 32 + kb * 16;
            uint32_t ah[2][4], al[2][4], bh[4][2], bl[4][2];
#pragma unroll
            for (int mt = 0; mt < 2; ++mt) {
                uint32_t off = (uint32_t)(((wm + mt * 16 + mrow) * AP + k0 + kcol8) * 2);
                ldsm4(ah[mt], abase_h + off);
                ldsm4(al[mt], abase_l + off);
            }
#pragma unroll
            for (int nt = 0; nt < 4; ++nt) {
                int n = wn + nt * 8 + g;
                int w0 = n * BPW + sg * 16 + kb * 8 + t4;
                bh[nt][0] = BH[w0];  bh[nt][1] = BH[w0 + 4];
                bl[nt][0] = BL[w0];  bl[nt][1] = BL[w0 + 4];
            }
#pragma unroll
            for (int mt = 0; mt < 2; ++mt)
#pragma unroll
                for (int nt = 0; nt < 4; ++nt) mma_bf16(acc[mt][nt], ah[mt], bh[nt]);
#pragma unroll
            for (int mt = 0; mt < 2; ++mt)
#pragma unroll
                for (int nt = 0; nt < 4; ++nt) mma_bf16(acc[mt][nt], ah[mt], bl[nt]);
#pragma unroll
            for (int mt = 0; mt < 2; ++mt)
#pragma unroll
                for (int nt = 0; nt < 4; ++nt) mma_bf16(acc[mt][nt], al[mt], bh[nt]);
        }
    };

    load_chunk(0, 0); cp_commit();
    load_chunk(1, 1); cp_commit();
    load_chunk(2, 2); cp_commit();
#pragma unroll 1
    for (int ch = 0; ch < NCH; ++ch) {
        asm volatile("cp.async.wait_group 2;" ::: "memory");
        __syncthreads();
        if (ch + 3 < NCH) load_chunk(ch + 3, (ch + 3) & 3);
        cp_commit();
        compute(ch & 3);
    }

    // k-split reduction via smem (stage buffers dead now), then scaled store
    __syncthreads();
    float* red = (float*)smem;   // [128][RP]
    if (sg == 1) {
#pragma unroll
        for (int mt = 0; mt < 2; ++mt) {
            const int r = wm + mt * 16 + g;
#pragma unroll
            for (int nt = 0; nt < 4; ++nt) {
                const int c = wn + nt * 8 + 2 * t4;
                red[r * RP + c]           = acc[mt][nt][0];
                red[r * RP + c + 1]       = acc[mt][nt][1];
                red[(r + 8) * RP + c]     = acc[mt][nt][2];
                red[(r + 8) * RP + c + 1] = acc[mt][nt][3];
            }
        }
    }
    __syncthreads();
    if (sg == 0) {
#pragma unroll
        for (int mt = 0; mt < 2; ++mt) {
            const int r = wm + mt * 16 + g;
            const int v = v0 + r;
            const float dlo = g_dv[v];
            const float dhi = g_dv[v + 8];
#pragma unroll
            for (int nt = 0; nt < 4; ++nt) {
                const int c = wn + nt * 8 + 2 * t4;
                float2 lo = make_float2(dlo * (acc[mt][nt][0] + red[r * RP + c]),
                                        dlo * (acc[mt][nt][1] + red[r * RP + c + 1]));
                float2 hi = make_float2(dhi * (acc[mt][nt][2] + red[(r + 8) * RP + c]),
                                        dhi * (acc[mt][nt][3] + red[(r + 8) * RP + c + 1]));
                *reinterpret_cast<float2*>(&out[(size_t)v * DF + c]) = lo;
                *reinterpret_cast<float2*>(&out[(size_t)(v + 8) * DF + c]) = hi;
            }
        }
    }
}

// ---------------- launch ----------------
extern "C" void kernel_launch(void* const* d_in, const int* in_sizes, int n_in,
                              void* d_out, int out_size) {
    const float* H = (const float*)d_in[0];
    const float* X = (const float*)d_in[1];
    float* out = (float*)d_out;

    // dynamic smem:
    // gemm1 = 4*(2*8704*2) + 4*(2*2304*4) = 139264 + 73728 = 212992 B
    // gemm2 = 4*(2*9216*2) + 4*(2*2304*4) = 147456 + 73728 = 221184 B
    static bool attr_done = false;
    if (!attr_done) {
        cudaFuncSetAttribute(k_gemm1, cudaFuncAttributeMaxDynamicSharedMemorySize, 212992);
        cudaFuncSetAttribute(k_gemm2, cudaFuncAttributeMaxDynamicSharedMemorySize, 221184);
        attr_done = true;
    }

    void* de_ptr = nullptr;
    cudaGetSymbolAddress(&de_ptr, g_de);
    cudaMemsetAsync(de_ptr, 0, NE * sizeof(float));

    k_deg<<<128, 512>>>(H, X);
    dim3 grid1(NE / 128, 2);
    k_gemm1<<<grid1, 512, 212992>>>();
    k_scale_y<<<(NE * DF) / 256, 256>>>();
    k_gemm2<<<NN / 128, 512, 221184>>>(out);
}